// round 1
// baseline (speedup 1.0000x reference)
#include <cuda_runtime.h>
#include <math.h>

// ---------------- problem constants ----------------
#define B_SZ   1024
#define N_NODE 64
#define F_DIM  256
#define HHEADS 4
#define DH     64
#define NLAYER 4
#define MROWS  (B_SZ * N_NODE)        // 65536
#define VELEMS ((size_t)B_SZ * NLAYER * N_NODE * F_DIM)   // 67,108,864
#define AELEMS ((size_t)B_SZ * N_NODE * N_NODE)           // 4,194,304

// ---------------- scratch (static device globals; no allocation) ----------------
__device__ float g_Q[(size_t)MROWS * F_DIM];
__device__ float g_K[(size_t)MROWS * F_DIM];
__device__ float g_Z[(size_t)MROWS * 3 * F_DIM];

// ---------------- tiled fp32 GEMM: C(M x 256) = A(M x K) @ B(K x 256) ----------------
// BM=128 BN=128 BK=16, 256 threads, 8x8 microtile.
#define BM 128
#define BN 128
#define BKT 16
#define TM 8
#define TN 8

template<bool BIAS, bool RELU, bool VOUT>
__global__ __launch_bounds__(256) void gemm_k(
    const float* __restrict__ A, const float* __restrict__ Bm,
    const float* __restrict__ bias, float* __restrict__ C,
    int K, int layer)
{
    __shared__ float As[BKT][BM];
    __shared__ float Bs[BKT][BN];

    const int tid = threadIdx.x;
    const int m0 = blockIdx.y * BM;
    const int n0 = blockIdx.x * BN;
    const int Ncols = 256;

    float acc[TM][TN];
#pragma unroll
    for (int i = 0; i < TM; ++i)
#pragma unroll
        for (int j = 0; j < TN; ++j) acc[i][j] = 0.f;

    const int ty = tid >> 4;   // 0..15 (M dir)
    const int tx = tid & 15;   // 0..15 (N dir)

    for (int k0 = 0; k0 < K; k0 += BKT) {
        // load A tile: 128x16 = 512 float4 (4 per row), 2 per thread
#pragma unroll
        for (int i = 0; i < 2; ++i) {
            int e  = tid * 2 + i;        // 0..511
            int m  = e >> 2;             // 0..127
            int kq = e & 3;              // float4 index in row
            float4 v = *reinterpret_cast<const float4*>(
                A + (size_t)(m0 + m) * K + k0 + kq * 4);
            As[kq * 4 + 0][m] = v.x;
            As[kq * 4 + 1][m] = v.y;
            As[kq * 4 + 2][m] = v.z;
            As[kq * 4 + 3][m] = v.w;
        }
        // load B tile: 16x128 = 512 float4 (32 per row)
#pragma unroll
        for (int i = 0; i < 2; ++i) {
            int e  = tid * 2 + i;
            int kk = e >> 5;             // 0..15
            int nq = e & 31;             // 0..31
            float4 v = *reinterpret_cast<const float4*>(
                Bm + (size_t)(k0 + kk) * Ncols + n0 + nq * 4);
            *reinterpret_cast<float4*>(&Bs[kk][nq * 4]) = v;
        }
        __syncthreads();

#pragma unroll
        for (int kk = 0; kk < BKT; ++kk) {
            float ra[TM], rb[TN];
#pragma unroll
            for (int i = 0; i < TM; ++i) ra[i] = As[kk][ty * TM + i];
#pragma unroll
            for (int j = 0; j < TN; ++j) rb[j] = Bs[kk][tx * TN + j];
#pragma unroll
            for (int i = 0; i < TM; ++i)
#pragma unroll
                for (int j = 0; j < TN; ++j) acc[i][j] += ra[i] * rb[j];
        }
        __syncthreads();
    }

    // epilogue
    float bv[TN];
    if (BIAS) {
#pragma unroll
        for (int j = 0; j < TN; ++j) bv[j] = bias[n0 + tx * TN + j];
    }
#pragma unroll
    for (int i = 0; i < TM; ++i) {
        int m = m0 + ty * TM + i;
        float vals[TN];
#pragma unroll
        for (int j = 0; j < TN; ++j) {
            float v = acc[i][j];
            if (BIAS) v += bv[j];
            if (RELU) v = fmaxf(v, 0.f);
            vals[j] = v;
        }
        size_t off;
        if (VOUT) {
            int bb = m >> 6;
            int nn = m & 63;
            off = (size_t)bb * (NLAYER * N_NODE * F_DIM)
                + (size_t)layer * (N_NODE * F_DIM)
                + (size_t)nn * F_DIM + n0 + tx * TN;
        } else {
            off = (size_t)m * 256 + n0 + tx * TN;
        }
        float4* p = reinterpret_cast<float4*>(C + off);
        p[0] = make_float4(vals[0], vals[1], vals[2], vals[3]);
        p[1] = make_float4(vals[4], vals[5], vals[6], vals[7]);
    }
}

// ---------------- attention -> normalized adjacency A (one block per batch) ----------------
__global__ __launch_bounds__(256) void attn_k(
    const float* __restrict__ Q, const float* __restrict__ Kmat,
    float* __restrict__ Aout)
{
    extern __shared__ float sm[];
    float* qs  = sm;            // 64*64
    float* ks  = sm + 4096;     // 64*64
    float* adj = sm + 8192;     // 64*64
    __shared__ float deg[64];

    const int b = blockIdx.x;
    const int t = threadIdx.x;
    const int i = t >> 2;   // query row 0..63
    const int g = t & 3;    // column group (16 cols each)

    for (int e = t; e < 4096; e += 256) adj[e] = 0.f;

    for (int h = 0; h < HHEADS; ++h) {
        __syncthreads();   // adj writes / prev tiles done before reload
        for (int e = t; e < 4096; e += 256) {
            int n = e >> 6, d = e & 63;
            size_t base = ((size_t)b * N_NODE + n) * F_DIM + h * DH + d;
            qs[e] = Q[base];
            ks[e] = Kmat[base];
        }
        __syncthreads();

        float s[16];
#pragma unroll
        for (int jj = 0; jj < 16; ++jj) s[jj] = 0.f;
        for (int d = 0; d < 64; ++d) {
            float qv = qs[i * 64 + d];
#pragma unroll
            for (int jj = 0; jj < 16; ++jj)
                s[jj] += qv * ks[(g * 16 + jj) * 64 + d];
        }
        // scores * (1/sqrt(64)) * 1e9
        float mx = -INFINITY;
#pragma unroll
        for (int jj = 0; jj < 16; ++jj) { s[jj] *= 1.25e8f; mx = fmaxf(mx, s[jj]); }
        mx = fmaxf(mx, __shfl_xor_sync(0xffffffffu, mx, 1));
        mx = fmaxf(mx, __shfl_xor_sync(0xffffffffu, mx, 2));
        float sum = 0.f;
#pragma unroll
        for (int jj = 0; jj < 16; ++jj) { s[jj] = __expf(s[jj] - mx); sum += s[jj]; }
        sum += __shfl_xor_sync(0xffffffffu, sum, 1);
        sum += __shfl_xor_sync(0xffffffffu, sum, 2);
        float inv = 0.25f / sum;   // 0.25 = mean over 4 heads
#pragma unroll
        for (int jj = 0; jj < 16; ++jj)
            adj[i * 64 + g * 16 + jj] += s[jj] * inv;
    }
    __syncthreads();

    // symmetrize
    float sv[16];
#pragma unroll
    for (int jj = 0; jj < 16; ++jj) {
        int j = g * 16 + jj;
        sv[jj] = 0.5f * (adj[i * 64 + j] + adj[j * 64 + i]);
    }
    __syncthreads();
#pragma unroll
    for (int jj = 0; jj < 16; ++jj) adj[i * 64 + g * 16 + jj] = sv[jj];

    float ds = 0.f;
#pragma unroll
    for (int jj = 0; jj < 16; ++jj) ds += sv[jj];
    ds += __shfl_xor_sync(0xffffffffu, ds, 1);
    ds += __shfl_xor_sync(0xffffffffu, ds, 2);
    if (g == 0) deg[i] = rsqrtf(ds);
    __syncthreads();

    float di = deg[i];
#pragma unroll
    for (int jj = 0; jj < 16; ++jj) {
        int j = g * 16 + jj;
        Aout[(size_t)b * 4096 + i * 64 + j] = di * adj[i * 64 + j] * deg[j];
    }
}

// ---------------- Chebyshev Z build: Zcat = [h, Lt@h, 2*Lt@(Lt@h) - h] ----------------
__global__ __launch_bounds__(256) void cheb_z_k(
    const float* __restrict__ Aglob, const float* __restrict__ hbase,
    long hBatchStride, float* __restrict__ Z)
{
    extern __shared__ float sm[];
    float* Lt = sm;                 // 64*64
    float* hs = sm + 4096;          // 64*256
    float* z1 = sm + 4096 + 16384;  // 64*256

    const int b = blockIdx.x;
    const int t = threadIdx.x;

    for (int e = t; e < 4096; e += 256) Lt[e] = -Aglob[(size_t)b * 4096 + e];
    const float* hb = hbase + (size_t)b * hBatchStride;
    for (int e = t; e < 16384; e += 256) hs[e] = hb[e];
    __syncthreads();

    const int f = t;   // 256 threads == 256 feature columns
    // Z1 = Lt @ h
    for (int c = 0; c < 8; ++c) {
        float acc[8];
#pragma unroll
        for (int r = 0; r < 8; ++r) acc[r] = 0.f;
        for (int j = 0; j < 64; ++j) {
            float hv = hs[j * 256 + f];
#pragma unroll
            for (int r = 0; r < 8; ++r) acc[r] += Lt[(c * 8 + r) * 64 + j] * hv;
        }
#pragma unroll
        for (int r = 0; r < 8; ++r) z1[(c * 8 + r) * 256 + f] = acc[r];
    }
    __syncthreads();

    float* Zb = Z + (size_t)b * N_NODE * 768;
    for (int c = 0; c < 8; ++c) {
        float acc[8];
#pragma unroll
        for (int r = 0; r < 8; ++r) acc[r] = 0.f;
        for (int j = 0; j < 64; ++j) {
            float zv = z1[j * 256 + f];
#pragma unroll
            for (int r = 0; r < 8; ++r) acc[r] += Lt[(c * 8 + r) * 64 + j] * zv;
        }
#pragma unroll
        for (int r = 0; r < 8; ++r) {
            int n = c * 8 + r;
            Zb[(size_t)n * 768 + f]       = hs[n * 256 + f];
            Zb[(size_t)n * 768 + 256 + f] = z1[n * 256 + f];
            Zb[(size_t)n * 768 + 512 + f] = 2.f * acc[r] - hs[n * 256 + f];
        }
    }
}

// ---------------- launcher ----------------
extern "C" void kernel_launch(void* const* d_in, const int* in_sizes, int n_in,
                              void* d_out, int out_size)
{
    const float* x     = (const float*)d_in[0];
    const float* Wq    = (const float*)d_in[1];
    const float* bq    = (const float*)d_in[2];
    const float* Wk    = (const float*)d_in[3];
    const float* bk    = (const float*)d_in[4];
    const float* theta = (const float*)d_in[5];

    float* out  = (float*)d_out;
    float* Vout = out;             // (B, 4, N, F)
    float* Aout = out + VELEMS;    // (B, N, N)

    float *Qb, *Kb, *Zb;
    cudaGetSymbolAddress((void**)&Qb, g_Q);
    cudaGetSymbolAddress((void**)&Kb, g_K);
    cudaGetSymbolAddress((void**)&Zb, g_Z);

    // opt-in large dynamic smem
    cudaFuncSetAttribute(attn_k, cudaFuncAttributeMaxDynamicSharedMemorySize, 49152);
    cudaFuncSetAttribute(cheb_z_k, cudaFuncAttributeMaxDynamicSharedMemorySize, 147456);

    dim3 gGrid(256 / BN, MROWS / BM);   // (2, 512)

    // Q/K projections
    gemm_k<true,  false, false><<<gGrid, 256>>>(x, Wq, bq, Qb, 256, 0);
    gemm_k<true,  false, false><<<gGrid, 256>>>(x, Wk, bk, Kb, 256, 0);

    // attention -> A
    attn_k<<<B_SZ, 256, 49152>>>(Qb, Kb, Aout);

    // 4 Chebyshev layers
    for (int l = 0; l < NLAYER; ++l) {
        const float* hbase;
        long hStride;
        if (l == 0) { hbase = x; hStride = (long)N_NODE * F_DIM; }
        else {
            hbase = Vout + (size_t)(l - 1) * N_NODE * F_DIM;
            hStride = (long)NLAYER * N_NODE * F_DIM;
        }
        cheb_z_k<<<B_SZ, 256, 147456>>>(Aout, hbase, hStride, Zb);
        gemm_k<false, true, true><<<gGrid, 256>>>(
            Zb, theta + (size_t)l * 3 * F_DIM * F_DIM, nullptr, Vout, 768, l);
    }
}

// round 2
// speedup vs baseline: 1.1889x; 1.1889x over previous
#include <cuda_runtime.h>
#include <math.h>

// ---------------- problem constants ----------------
#define B_SZ   1024
#define N_NODE 64
#define F_DIM  256
#define HHEADS 4
#define DH     64
#define NLAYER 4
#define MROWS  (B_SZ * N_NODE)                              // 65536
#define VELEMS ((size_t)B_SZ * NLAYER * N_NODE * F_DIM)     // 67,108,864

typedef unsigned long long ull;

// ---------------- packed f32x2 helpers ----------------
__device__ __forceinline__ ull ffma2(ull a, ull b, ull c) {
    ull d;
    asm("fma.rn.f32x2 %0, %1, %2, %3;" : "=l"(d) : "l"(a), "l"(b), "l"(c));
    return d;
}
__device__ __forceinline__ ull dup2(float x) {
    ull d;
    asm("mov.b64 %0, {%1, %1};" : "=l"(d) : "f"(x));
    return d;
}
__device__ __forceinline__ void upk2(ull v, float& lo, float& hi) {
    asm("mov.b64 {%0, %1}, %2;" : "=f"(lo), "=f"(hi) : "l"(v));
}

// ---------------- scratch (static device globals; no allocation) ----------------
__device__ float g_Q[(size_t)MROWS * F_DIM];
__device__ float g_K[(size_t)MROWS * F_DIM];

// ---------------- Q/K projection GEMM: C(M x 256) = A(M x 256) @ B(256 x 256) + bias ----------------
#define BM 128
#define BN 128
#define BKT 16
#define TM 8
#define TN 8

__global__ __launch_bounds__(256) void gemm_qk(
    const float* __restrict__ A, const float* __restrict__ Bm,
    const float* __restrict__ bias, float* __restrict__ C)
{
    __shared__ float As[BKT][BM];
    __shared__ float Bs[BKT][BN];

    const int tid = threadIdx.x;
    const int m0 = blockIdx.y * BM;
    const int n0 = blockIdx.x * BN;
    const int K = 256, Ncols = 256;

    ull acc[TM][TN / 2];
#pragma unroll
    for (int i = 0; i < TM; ++i)
#pragma unroll
        for (int j = 0; j < TN / 2; ++j) acc[i][j] = 0ull;

    const int ty = tid >> 4;   // 0..15
    const int tx = tid & 15;   // 0..15

    for (int k0 = 0; k0 < K; k0 += BKT) {
#pragma unroll
        for (int i = 0; i < 2; ++i) {
            int e  = tid * 2 + i;
            int m  = e >> 2;
            int kq = e & 3;
            float4 v = *reinterpret_cast<const float4*>(
                A + (size_t)(m0 + m) * K + k0 + kq * 4);
            As[kq * 4 + 0][m] = v.x;
            As[kq * 4 + 1][m] = v.y;
            As[kq * 4 + 2][m] = v.z;
            As[kq * 4 + 3][m] = v.w;
        }
#pragma unroll
        for (int i = 0; i < 2; ++i) {
            int e  = tid * 2 + i;
            int kk = e >> 5;
            int nq = e & 31;
            float4 v = *reinterpret_cast<const float4*>(
                Bm + (size_t)(k0 + kk) * Ncols + n0 + nq * 4);
            *reinterpret_cast<float4*>(&Bs[kk][nq * 4]) = v;
        }
        __syncthreads();

#pragma unroll
        for (int kk = 0; kk < BKT; ++kk) {
            float4 a0 = *reinterpret_cast<const float4*>(&As[kk][ty * TM]);
            float4 a1 = *reinterpret_cast<const float4*>(&As[kk][ty * TM + 4]);
            ulonglong2 b0 = *reinterpret_cast<const ulonglong2*>(&Bs[kk][tx * TN]);
            ulonglong2 b1 = *reinterpret_cast<const ulonglong2*>(&Bs[kk][tx * TN + 4]);
            float av[TM] = {a0.x, a0.y, a0.z, a0.w, a1.x, a1.y, a1.z, a1.w};
#pragma unroll
            for (int i = 0; i < TM; ++i) {
                ull ad = dup2(av[i]);
                acc[i][0] = ffma2(ad, b0.x, acc[i][0]);
                acc[i][1] = ffma2(ad, b0.y, acc[i][1]);
                acc[i][2] = ffma2(ad, b1.x, acc[i][2]);
                acc[i][3] = ffma2(ad, b1.y, acc[i][3]);
            }
        }
        __syncthreads();
    }

    float bv[TN];
#pragma unroll
    for (int j = 0; j < TN; ++j) bv[j] = bias[n0 + tx * TN + j];

#pragma unroll
    for (int i = 0; i < TM; ++i) {
        int m = m0 + ty * TM + i;
        float v[TN];
#pragma unroll
        for (int j = 0; j < TN / 2; ++j) upk2(acc[i][j], v[j * 2], v[j * 2 + 1]);
#pragma unroll
        for (int j = 0; j < TN; ++j) v[j] += bv[j];
        float4* p = reinterpret_cast<float4*>(C + (size_t)m * 256 + n0 + tx * TN);
        p[0] = make_float4(v[0], v[1], v[2], v[3]);
        p[1] = make_float4(v[4], v[5], v[6], v[7]);
    }
}

// ---------------- attention -> normalized adjacency A (one block per batch) ----------------
__global__ __launch_bounds__(256) void attn_k(
    const float* __restrict__ Q, const float* __restrict__ Kmat,
    float* __restrict__ Aout)
{
    extern __shared__ float sm[];
    float* qs  = sm;            // 64*64
    float* ks  = sm + 4096;     // 64*64
    float* adj = sm + 8192;     // 64*64
    __shared__ float deg[64];

    const int b = blockIdx.x;
    const int t = threadIdx.x;
    const int i = t >> 2;
    const int g = t & 3;

    for (int e = t; e < 4096; e += 256) adj[e] = 0.f;

    for (int h = 0; h < HHEADS; ++h) {
        __syncthreads();
        for (int e = t; e < 4096; e += 256) {
            int n = e >> 6, d = e & 63;
            size_t base = ((size_t)b * N_NODE + n) * F_DIM + h * DH + d;
            qs[e] = Q[base];
            ks[e] = Kmat[base];
        }
        __syncthreads();

        float s[16];
#pragma unroll
        for (int jj = 0; jj < 16; ++jj) s[jj] = 0.f;
        for (int d = 0; d < 64; ++d) {
            float qv = qs[i * 64 + d];
#pragma unroll
            for (int jj = 0; jj < 16; ++jj)
                s[jj] += qv * ks[(g * 16 + jj) * 64 + d];
        }
        float mx = -INFINITY;
#pragma unroll
        for (int jj = 0; jj < 16; ++jj) { s[jj] *= 1.25e8f; mx = fmaxf(mx, s[jj]); }
        mx = fmaxf(mx, __shfl_xor_sync(0xffffffffu, mx, 1));
        mx = fmaxf(mx, __shfl_xor_sync(0xffffffffu, mx, 2));
        float sum = 0.f;
#pragma unroll
        for (int jj = 0; jj < 16; ++jj) { s[jj] = __expf(s[jj] - mx); sum += s[jj]; }
        sum += __shfl_xor_sync(0xffffffffu, sum, 1);
        sum += __shfl_xor_sync(0xffffffffu, sum, 2);
        float inv = 0.25f / sum;
#pragma unroll
        for (int jj = 0; jj < 16; ++jj)
            adj[i * 64 + g * 16 + jj] += s[jj] * inv;
    }
    __syncthreads();

    float sv[16];
#pragma unroll
    for (int jj = 0; jj < 16; ++jj) {
        int j = g * 16 + jj;
        sv[jj] = 0.5f * (adj[i * 64 + j] + adj[j * 64 + i]);
    }
    __syncthreads();
#pragma unroll
    for (int jj = 0; jj < 16; ++jj) adj[i * 64 + g * 16 + jj] = sv[jj];

    float ds = 0.f;
#pragma unroll
    for (int jj = 0; jj < 16; ++jj) ds += sv[jj];
    ds += __shfl_xor_sync(0xffffffffu, ds, 1);
    ds += __shfl_xor_sync(0xffffffffu, ds, 2);
    if (g == 0) deg[i] = rsqrtf(ds);
    __syncthreads();

    float di = deg[i];
#pragma unroll
    for (int jj = 0; jj < 16; ++jj) {
        int j = g * 16 + jj;
        Aout[(size_t)b * 4096 + i * 64 + j] = di * adj[i * 64 + j] * deg[j];
    }
}

// ---------------- fused 4-layer Chebyshev GCN (one block per batch, all layers) ----------------
// smem: Lt(4096) hs(16384) z1(16384) z2(16384) theta-stage(2*2048) = 57344 floats = 224 KB
__global__ __launch_bounds__(512, 1) void fused_gcn_k(
    const float* __restrict__ Aglob, const float* __restrict__ x,
    const float* __restrict__ theta, float* __restrict__ Vout)
{
    extern __shared__ float sm[];
    float* Lt = sm;                  // 64*64
    float* hs = sm + 4096;           // 64*256
    float* z1 = sm + 20480;          // 64*256
    float* z2 = sm + 36864;          // 64*256
    float* th = sm + 53248;          // 2 * (8*256)

    const int b = blockIdx.x;
    const int t = threadIdx.x;

    // load Lt = -A[b]
    {
        const float4* Ab = reinterpret_cast<const float4*>(Aglob + (size_t)b * 4096);
        float4* Ld = reinterpret_cast<float4*>(Lt);
        for (int e = t; e < 1024; e += 512) {
            float4 v = Ab[e];
            Ld[e] = make_float4(-v.x, -v.y, -v.z, -v.w);
        }
    }
    // load h = x[b]
    {
        const float4* xb = reinterpret_cast<const float4*>(x + (size_t)b * 16384);
        float4* hd = reinterpret_cast<float4*>(hs);
        for (int e = t; e < 4096; e += 512) hd[e] = xb[e];
    }

    const int fp = t & 127;          // feature-pair index (z-build)
    const int q4 = t >> 7;           // row quarter (z-build)
    const int ty = t >> 6;           // GEMM row group (8 rows)
    const int tx = t & 63;           // GEMM col group (4 cols)
    const int lrow = t >> 6;         // theta stage row
    const int lcol = (t & 63) * 4;   // theta stage col

    for (int l = 0; l < NLAYER; ++l) {
        const float* TH = theta + (size_t)l * 768 * 256;
        __syncthreads();   // hs (and Lt) ready

        // ---- z1 = Lt @ h ----
        {
            ull acc[16];
#pragma unroll
            for (int p = 0; p < 16; ++p) acc[p] = 0ull;
            for (int j = 0; j < 64; j += 4) {
                ull h0 = *reinterpret_cast<const ull*>(&hs[(j + 0) * 256 + fp * 2]);
                ull h1 = *reinterpret_cast<const ull*>(&hs[(j + 1) * 256 + fp * 2]);
                ull h2 = *reinterpret_cast<const ull*>(&hs[(j + 2) * 256 + fp * 2]);
                ull h3 = *reinterpret_cast<const ull*>(&hs[(j + 3) * 256 + fp * 2]);
#pragma unroll
                for (int r = 0; r < 16; ++r) {
                    float4 lt = *reinterpret_cast<const float4*>(&Lt[(q4 * 16 + r) * 64 + j]);
                    acc[r] = ffma2(dup2(lt.x), h0, acc[r]);
                    acc[r] = ffma2(dup2(lt.y), h1, acc[r]);
                    acc[r] = ffma2(dup2(lt.z), h2, acc[r]);
                    acc[r] = ffma2(dup2(lt.w), h3, acc[r]);
                }
            }
#pragma unroll
            for (int r = 0; r < 16; ++r)
                *reinterpret_cast<ull*>(&z1[(q4 * 16 + r) * 256 + fp * 2]) = acc[r];
        }
        __syncthreads();

        // ---- z2 = 2 * Lt @ z1 - h ----
        {
            ull acc[16];
#pragma unroll
            for (int p = 0; p < 16; ++p) acc[p] = 0ull;
            for (int j = 0; j < 64; j += 4) {
                ull h0 = *reinterpret_cast<const ull*>(&z1[(j + 0) * 256 + fp * 2]);
                ull h1 = *reinterpret_cast<const ull*>(&z1[(j + 1) * 256 + fp * 2]);
                ull h2 = *reinterpret_cast<const ull*>(&z1[(j + 2) * 256 + fp * 2]);
                ull h3 = *reinterpret_cast<const ull*>(&z1[(j + 3) * 256 + fp * 2]);
#pragma unroll
                for (int r = 0; r < 16; ++r) {
                    float4 lt = *reinterpret_cast<const float4*>(&Lt[(q4 * 16 + r) * 64 + j]);
                    acc[r] = ffma2(dup2(lt.x), h0, acc[r]);
                    acc[r] = ffma2(dup2(lt.y), h1, acc[r]);
                    acc[r] = ffma2(dup2(lt.z), h2, acc[r]);
                    acc[r] = ffma2(dup2(lt.w), h3, acc[r]);
                }
            }
#pragma unroll
            for (int r = 0; r < 16; ++r) {
                int idx = (q4 * 16 + r) * 256 + fp * 2;
                float lo, hi;
                upk2(acc[r], lo, hi);
                z2[idx]     = 2.f * lo - hs[idx];
                z2[idx + 1] = 2.f * hi - hs[idx + 1];
            }
        }

        // ---- out = zcat @ theta_l  (96 chunks of 8 k-rows, double-buffered) ----
        ull acc[8][2];
#pragma unroll
        for (int i = 0; i < 8; ++i) { acc[i][0] = 0ull; acc[i][1] = 0ull; }

        float4 pf = *reinterpret_cast<const float4*>(&TH[(size_t)lrow * 256 + lcol]);
        *reinterpret_cast<float4*>(&th[lrow * 256 + lcol]) = pf;

        for (int c = 0; c < 96; ++c) {
            if (c < 95)
                pf = *reinterpret_cast<const float4*>(
                    &TH[(size_t)((c + 1) * 8 + lrow) * 256 + lcol]);
            __syncthreads();   // stage(c) written; z2 ready on first iter

            const float* tb = th + (c & 1) * 2048;
            const float* zsrc = (c < 32) ? hs : (c < 64) ? z1 : z2;
            const int k0 = (c & 31) * 8;

#pragma unroll
            for (int g = 0; g < 2; ++g) {
                const int kb = k0 + g * 4;
                float4 ra[8];
#pragma unroll
                for (int i = 0; i < 8; ++i)
                    ra[i] = *reinterpret_cast<const float4*>(&zsrc[(ty * 8 + i) * 256 + kb]);
#pragma unroll
                for (int kk = 0; kk < 4; ++kk) {
                    ulonglong2 rb = *reinterpret_cast<const ulonglong2*>(
                        &tb[(g * 4 + kk) * 256 + tx * 4]);
#pragma unroll
                    for (int i = 0; i < 8; ++i) {
                        float a = (kk == 0) ? ra[i].x : (kk == 1) ? ra[i].y
                                 : (kk == 2) ? ra[i].z : ra[i].w;
                        ull ad = dup2(a);
                        acc[i][0] = ffma2(ad, rb.x, acc[i][0]);
                        acc[i][1] = ffma2(ad, rb.y, acc[i][1]);
                    }
                }
            }
            if (c < 95)
                *reinterpret_cast<float4*>(&th[((c + 1) & 1) * 2048 + lrow * 256 + lcol]) = pf;
        }
        __syncthreads();   // all GEMM reads of hs/z1/z2 done

        // ---- epilogue: relu, write V, update h in smem ----
        float* Vb = Vout + (size_t)b * (NLAYER * 16384) + (size_t)l * 16384;
#pragma unroll
        for (int i = 0; i < 8; ++i) {
            int n = ty * 8 + i;
            float v0, v1, v2, v3;
            upk2(acc[i][0], v0, v1);
            upk2(acc[i][1], v2, v3);
            v0 = fmaxf(v0, 0.f); v1 = fmaxf(v1, 0.f);
            v2 = fmaxf(v2, 0.f); v3 = fmaxf(v3, 0.f);
            float4 vv = make_float4(v0, v1, v2, v3);
            *reinterpret_cast<float4*>(&hs[n * 256 + tx * 4]) = vv;
            *reinterpret_cast<float4*>(&Vb[n * 256 + tx * 4]) = vv;
        }
    }
}

// ---------------- launcher ----------------
extern "C" void kernel_launch(void* const* d_in, const int* in_sizes, int n_in,
                              void* d_out, int out_size)
{
    const float* x     = (const float*)d_in[0];
    const float* Wq    = (const float*)d_in[1];
    const float* bq    = (const float*)d_in[2];
    const float* Wk    = (const float*)d_in[3];
    const float* bk    = (const float*)d_in[4];
    const float* theta = (const float*)d_in[5];

    float* out  = (float*)d_out;
    float* Vout = out;             // (B, 4, N, F)
    float* Aout = out + VELEMS;    // (B, N, N)

    float *Qb, *Kb;
    cudaGetSymbolAddress((void**)&Qb, g_Q);
    cudaGetSymbolAddress((void**)&Kb, g_K);

    cudaFuncSetAttribute(attn_k, cudaFuncAttributeMaxDynamicSharedMemorySize, 49152);
    cudaFuncSetAttribute(fused_gcn_k, cudaFuncAttributeMaxDynamicSharedMemorySize, 229376);

    dim3 gGrid(256 / BN, MROWS / BM);   // (2, 512)

    gemm_qk<<<gGrid, 256>>>(x, Wq, bq, Qb);
    gemm_qk<<<gGrid, 256>>>(x, Wk, bk, Kb);

    attn_k<<<B_SZ, 256, 49152>>>(Qb, Kb, Aout);

    fused_gcn_k<<<B_SZ, 512, 229376>>>(Aout, x, theta, Vout);
}

// round 5
// speedup vs baseline: 1.4889x; 1.2523x over previous
#include <cuda_runtime.h>
#include <cuda_bf16.h>
#include <math.h>
#include <stdint.h>

typedef unsigned long long ull;

#define B_SZ   1024
#define NLAYER 4
#define MROWS  65536
#define VELEMS ((size_t)B_SZ * NLAYER * 64 * 256)

// ---------------- scratch (static device globals; no allocation) ----------------
__device__ __align__(16) __nv_bfloat16 g_Zhi[(size_t)MROWS * 768];
__device__ __align__(16) __nv_bfloat16 g_Zlo[(size_t)MROWS * 768];
__device__ __align__(16) float         g_Q[(size_t)MROWS * 256];
__device__ __align__(16) float         g_K[(size_t)MROWS * 256];
__device__ __align__(16) __nv_bfloat16 g_THhi[4 * 256 * 768];
__device__ __align__(16) __nv_bfloat16 g_THlo[4 * 256 * 768];

// ---------------- helpers ----------------
__device__ __forceinline__ uint32_t smem_u32(const void* p) {
    uint32_t a;
    asm("{ .reg .u64 t; cvta.to.shared.u64 t, %1; cvt.u32.u64 %0, t; }" : "=r"(a) : "l"(p));
    return a;
}
__device__ __forceinline__ void ldsm_x4(uint32_t* r, uint32_t a) {
    asm volatile("ldmatrix.sync.aligned.m8n8.x4.shared.b16 {%0,%1,%2,%3}, [%4];"
                 : "=r"(r[0]), "=r"(r[1]), "=r"(r[2]), "=r"(r[3]) : "r"(a));
}
__device__ __forceinline__ void mma_bf16(float* d, const uint32_t* a, uint32_t b0, uint32_t b1) {
    asm volatile("mma.sync.aligned.m16n8k16.row.col.f32.bf16.bf16.f32 "
                 "{%0,%1,%2,%3}, {%4,%5,%6,%7}, {%8,%9}, {%0,%1,%2,%3};"
                 : "+f"(d[0]), "+f"(d[1]), "+f"(d[2]), "+f"(d[3])
                 : "r"(a[0]), "r"(a[1]), "r"(a[2]), "r"(a[3]), "r"(b0), "r"(b1));
}
__device__ __forceinline__ ull ffma2(ull a, ull b, ull c) {
    ull d; asm("fma.rn.f32x2 %0, %1, %2, %3;" : "=l"(d) : "l"(a), "l"(b), "l"(c));
    return d;
}
__device__ __forceinline__ ull dup2(float x) {
    ull d; asm("mov.b64 %0, {%1, %1};" : "=l"(d) : "f"(x)); return d;
}
__device__ __forceinline__ void upk2(ull v, float& lo, float& hi) {
    asm("mov.b64 {%0, %1}, %2;" : "=f"(lo), "=f"(hi) : "l"(v));
}
__device__ __forceinline__ void bsplit(float v, __nv_bfloat16& h, __nv_bfloat16& l) {
    h = __float2bfloat16(v);
    l = __float2bfloat16(v - __bfloat162float(h));
}

// ---------------- prep kernels ----------------
__global__ __launch_bounds__(256) void split_x_k(
    const float* __restrict__ x, __nv_bfloat16* __restrict__ zhi,
    __nv_bfloat16* __restrict__ zlo)
{
    int e = blockIdx.x * 256 + threadIdx.x;
    int m = e >> 6, q = e & 63;
    float4 v = reinterpret_cast<const float4*>(x)[e];
    __nv_bfloat16 h0, l0, h1, l1, h2, l2, h3, l3;
    bsplit(v.x, h0, l0); bsplit(v.y, h1, l1);
    bsplit(v.z, h2, l2); bsplit(v.w, h3, l3);
    size_t o = (size_t)m * 768 + q * 4;
    __nv_bfloat162 a; a.x = h0; a.y = h1;
    __nv_bfloat162 b; b.x = h2; b.y = h3;
    __nv_bfloat162 c; c.x = l0; c.y = l1;
    __nv_bfloat162 d; d.x = l2; d.y = l3;
    reinterpret_cast<__nv_bfloat162*>(zhi + o)[0] = a;
    reinterpret_cast<__nv_bfloat162*>(zhi + o)[1] = b;
    reinterpret_cast<__nv_bfloat162*>(zlo + o)[0] = c;
    reinterpret_cast<__nv_bfloat162*>(zlo + o)[1] = d;
}

__global__ __launch_bounds__(256) void prep_th_k(
    const float* __restrict__ theta,
    __nv_bfloat16* __restrict__ thi, __nv_bfloat16* __restrict__ tlo)
{
    int idx = blockIdx.x * 256 + threadIdx.x;   // 786432 total
    int l = idx / 196608, rem = idx % 196608;
    int n = rem / 768, k = rem % 768;
    float v = theta[(size_t)l * 196608 + (size_t)k * 256 + n];
    __nv_bfloat16 h, lo; bsplit(v, h, lo);
    thi[(size_t)l * 196608 + (size_t)n * 768 + k] = h;
    tlo[(size_t)l * 196608 + (size_t)n * 768 + k] = lo;
}

// ---------------- QK projection GEMM (fp32 FFMA2, proven) ----------------
#define BM 128
#define BN 128
#define BKT 16

__global__ __launch_bounds__(256) void gemm_qk(
    const float* __restrict__ A, const float* __restrict__ Bm,
    const float* __restrict__ bias, float* __restrict__ C)
{
    __shared__ float As[BKT][BM];
    __shared__ float Bs[BKT][BN];

    const int tid = threadIdx.x;
    const int m0 = blockIdx.y * BM;
    const int n0 = blockIdx.x * BN;

    ull acc[8][4];
#pragma unroll
    for (int i = 0; i < 8; ++i)
#pragma unroll
        for (int j = 0; j < 4; ++j) acc[i][j] = 0ull;

    const int ty = tid >> 4, tx = tid & 15;

    for (int k0 = 0; k0 < 256; k0 += BKT) {
#pragma unroll
        for (int i = 0; i < 2; ++i) {
            int e = tid * 2 + i, m = e >> 2, kq = e & 3;
            float4 v = *reinterpret_cast<const float4*>(A + (size_t)(m0 + m) * 256 + k0 + kq * 4);
            As[kq * 4 + 0][m] = v.x; As[kq * 4 + 1][m] = v.y;
            As[kq * 4 + 2][m] = v.z; As[kq * 4 + 3][m] = v.w;
        }
#pragma unroll
        for (int i = 0; i < 2; ++i) {
            int e = tid * 2 + i, kk = e >> 5, nq = e & 31;
            float4 v = *reinterpret_cast<const float4*>(Bm + (size_t)(k0 + kk) * 256 + n0 + nq * 4);
            *reinterpret_cast<float4*>(&Bs[kk][nq * 4]) = v;
        }
        __syncthreads();
#pragma unroll
        for (int kk = 0; kk < BKT; ++kk) {
            float4 a0 = *reinterpret_cast<const float4*>(&As[kk][ty * 8]);
            float4 a1 = *reinterpret_cast<const float4*>(&As[kk][ty * 8 + 4]);
            ulonglong2 b0 = *reinterpret_cast<const ulonglong2*>(&Bs[kk][tx * 8]);
            ulonglong2 b1 = *reinterpret_cast<const ulonglong2*>(&Bs[kk][tx * 8 + 4]);
            float av[8] = {a0.x, a0.y, a0.z, a0.w, a1.x, a1.y, a1.z, a1.w};
#pragma unroll
            for (int i = 0; i < 8; ++i) {
                ull ad = dup2(av[i]);
                acc[i][0] = ffma2(ad, b0.x, acc[i][0]);
                acc[i][1] = ffma2(ad, b0.y, acc[i][1]);
                acc[i][2] = ffma2(ad, b1.x, acc[i][2]);
                acc[i][3] = ffma2(ad, b1.y, acc[i][3]);
            }
        }
        __syncthreads();
    }

    float bv[8];
#pragma unroll
    for (int j = 0; j < 8; ++j) bv[j] = bias[n0 + tx * 8 + j];
#pragma unroll
    for (int i = 0; i < 8; ++i) {
        int m = m0 + ty * 8 + i;
        float v[8];
#pragma unroll
        for (int j = 0; j < 4; ++j) upk2(acc[i][j], v[j * 2], v[j * 2 + 1]);
#pragma unroll
        for (int j = 0; j < 8; ++j) v[j] += bv[j];
        float4* p = reinterpret_cast<float4*>(C + (size_t)m * 256 + n0 + tx * 8);
        p[0] = make_float4(v[0], v[1], v[2], v[3]);
        p[1] = make_float4(v[4], v[5], v[6], v[7]);
    }
}

// ---------------- attention -> normalized adjacency (proven) ----------------
__global__ __launch_bounds__(256) void attn_k(
    const float* __restrict__ Q, const float* __restrict__ Kmat,
    float* __restrict__ Aout)
{
    extern __shared__ float sm[];
    float* qs  = sm;
    float* ks  = sm + 4096;
    float* adj = sm + 8192;
    __shared__ float deg[64];

    const int b = blockIdx.x, t = threadIdx.x;
    const int i = t >> 2, g = t & 3;

    for (int e = t; e < 4096; e += 256) adj[e] = 0.f;

    for (int h = 0; h < 4; ++h) {
        __syncthreads();
        for (int e = t; e < 4096; e += 256) {
            int n = e >> 6, d = e & 63;
            size_t base = ((size_t)b * 64 + n) * 256 + h * 64 + d;
            qs[e] = Q[base];
            ks[e] = Kmat[base];
        }
        __syncthreads();

        float s[16];
#pragma unroll
        for (int jj = 0; jj < 16; ++jj) s[jj] = 0.f;
        for (int d = 0; d < 64; ++d) {
            float qv = qs[i * 64 + d];
#pragma unroll
            for (int jj = 0; jj < 16; ++jj)
                s[jj] += qv * ks[(g * 16 + jj) * 64 + d];
        }
        float mx = -INFINITY;
#pragma unroll
        for (int jj = 0; jj < 16; ++jj) { s[jj] *= 1.25e8f; mx = fmaxf(mx, s[jj]); }
        mx = fmaxf(mx, __shfl_xor_sync(0xffffffffu, mx, 1));
        mx = fmaxf(mx, __shfl_xor_sync(0xffffffffu, mx, 2));
        float sum = 0.f;
#pragma unroll
        for (int jj = 0; jj < 16; ++jj) { s[jj] = __expf(s[jj] - mx); sum += s[jj]; }
        sum += __shfl_xor_sync(0xffffffffu, sum, 1);
        sum += __shfl_xor_sync(0xffffffffu, sum, 2);
        float inv = 0.25f / sum;
#pragma unroll
        for (int jj = 0; jj < 16; ++jj)
            adj[i * 64 + g * 16 + jj] += s[jj] * inv;
    }
    __syncthreads();

    float sv[16];
#pragma unroll
    for (int jj = 0; jj < 16; ++jj) {
        int j = g * 16 + jj;
        sv[jj] = 0.5f * (adj[i * 64 + j] + adj[j * 64 + i]);
    }
    __syncthreads();
#pragma unroll
    for (int jj = 0; jj < 16; ++jj) adj[i * 64 + g * 16 + jj] = sv[jj];

    float ds = 0.f;
#pragma unroll
    for (int jj = 0; jj < 16; ++jj) ds += sv[jj];
    ds += __shfl_xor_sync(0xffffffffu, ds, 1);
    ds += __shfl_xor_sync(0xffffffffu, ds, 2);
    if (g == 0) deg[i] = rsqrtf(ds);
    __syncthreads();

    float di = deg[i];
#pragma unroll
    for (int jj = 0; jj < 16; ++jj) {
        int j = g * 16 + jj;
        Aout[(size_t)b * 4096 + i * 64 + j] = di * adj[i * 64 + j] * deg[j];
    }
}

// ---------------- Chebyshev z1/z2 build -> Z bf16 hi/lo cols 256..767 ----------------
__global__ __launch_bounds__(512) void cheb_k(
    const float* __restrict__ Aglob, const float* __restrict__ hbase, long hStride,
    __nv_bfloat16* __restrict__ zhi, __nv_bfloat16* __restrict__ zlo)
{
    extern __shared__ float sm[];
    float* Lt = sm;
    float* hs = sm + 4096;
    float* z1 = sm + 20480;

    const int b = blockIdx.x, t = threadIdx.x;

    {
        const float4* Ab = reinterpret_cast<const float4*>(Aglob + (size_t)b * 4096);
        float4* Ld = reinterpret_cast<float4*>(Lt);
        for (int e = t; e < 1024; e += 512) {
            float4 v = Ab[e];
            Ld[e] = make_float4(-v.x, -v.y, -v.z, -v.w);
        }
        const float4* hb = reinterpret_cast<const float4*>(hbase + (size_t)b * hStride);
        float4* hd = reinterpret_cast<float4*>(hs);
        for (int e = t; e < 4096; e += 512) hd[e] = hb[e];
    }
    __syncthreads();

    const int fp = t & 127, q4 = t >> 7;

    {
        ull acc[16];
#pragma unroll
        for (int p = 0; p < 16; ++p) acc[p] = 0ull;
        for (int j = 0; j < 64; j += 4) {
            ull h0 = *reinterpret_cast<const ull*>(&hs[(j + 0) * 256 + fp * 2]);
            ull h1 = *reinterpret_cast<const ull*>(&hs[(j + 1) * 256 + fp * 2]);
            ull h2 = *reinterpret_cast<const ull*>(&hs[(j + 2) * 256 + fp * 2]);
            ull h3 = *reinterpret_cast<const ull*>(&hs[(j + 3) * 256 + fp * 2]);
#pragma unroll
            for (int r = 0; r < 16; ++r) {
                float4 lt = *reinterpret_cast<const float4*>(&Lt[(q4 * 16 + r) * 64 + j]);
                acc[r] = ffma2(dup2(lt.x), h0, acc[r]);
                acc[r] = ffma2(dup2(lt.y), h1, acc[r]);
                acc[r] = ffma2(dup2(lt.z), h2, acc[r]);
                acc[r] = ffma2(dup2(lt.w), h3, acc[r]);
            }
        }
#pragma unroll
        for (int r = 0; r < 16; ++r) {
            int row = q4 * 16 + r;
            *reinterpret_cast<ull*>(&z1[row * 256 + fp * 2]) = acc[r];
            float lo_, hi_;
            upk2(acc[r], lo_, hi_);
            __nv_bfloat16 h0, l0, h1, l1;
            bsplit(lo_, h0, l0); bsplit(hi_, h1, l1);
            size_t zo = ((size_t)(b * 64 + row)) * 768 + 256 + fp * 2;
            __nv_bfloat162 ph; ph.x = h0; ph.y = h1;
            __nv_bfloat162 pl; pl.x = l0; pl.y = l1;
            *reinterpret_cast<__nv_bfloat162*>(zhi + zo) = ph;
            *reinterpret_cast<__nv_bfloat162*>(zlo + zo) = pl;
        }
    }
    __syncthreads();

    {
        ull acc[16];
#pragma unroll
        for (int p = 0; p < 16; ++p) acc[p] = 0ull;
        for (int j = 0; j < 64; j += 4) {
            ull h0 = *reinterpret_cast<const ull*>(&z1[(j + 0) * 256 + fp * 2]);
            ull h1 = *reinterpret_cast<const ull*>(&z1[(j + 1) * 256 + fp * 2]);
            ull h2 = *reinterpret_cast<const ull*>(&z1[(j + 2) * 256 + fp * 2]);
            ull h3 = *reinterpret_cast<const ull*>(&z1[(j + 3) * 256 + fp * 2]);
#pragma unroll
            for (int r = 0; r < 16; ++r) {
                float4 lt = *reinterpret_cast<const float4*>(&Lt[(q4 * 16 + r) * 64 + j]);
                acc[r] = ffma2(dup2(lt.x), h0, acc[r]);
                acc[r] = ffma2(dup2(lt.y), h1, acc[r]);
                acc[r] = ffma2(dup2(lt.z), h2, acc[r]);
                acc[r] = ffma2(dup2(lt.w), h3, acc[r]);
            }
        }
#pragma unroll
        for (int r = 0; r < 16; ++r) {
            int row = q4 * 16 + r;
            int idx = row * 256 + fp * 2;
            float lo_, hi_;
            upk2(acc[r], lo_, hi_);
            float v0 = 2.f * lo_ - hs[idx];
            float v1 = 2.f * hi_ - hs[idx + 1];
            __nv_bfloat16 h0, l0, h1, l1;
            bsplit(v0, h0, l0); bsplit(v1, h1, l1);
            size_t zo = ((size_t)(b * 64 + row)) * 768 + 512 + fp * 2;
            __nv_bfloat162 ph; ph.x = h0; ph.y = h1;
            __nv_bfloat162 pl; pl.x = l0; pl.y = l1;
            *reinterpret_cast<__nv_bfloat162*>(zhi + zo) = ph;
            *reinterpret_cast<__nv_bfloat162*>(zlo + zo) = pl;
        }
    }
}

// ---------------- theta GEMM: C(65536 x 256) = Z(65536 x 768) @ TH^T, bf16x3 mma ----------------
// Block 256 thr (8 warps, wm 0..3 x wn 0..1); tile M=128, N=64; K chunk 32 (24 chunks).
// smem (bf16 elems): Ahi[0), Alo[5120), Bhi[10240), Blo[12800); rows padded to 40 elems.
__global__ __launch_bounds__(256, 2) void theta_mma(
    const __nv_bfloat16* __restrict__ Zhi, const __nv_bfloat16* __restrict__ Zlo,
    const __nv_bfloat16* __restrict__ THh, const __nv_bfloat16* __restrict__ THl,
    float* __restrict__ Vout, __nv_bfloat16* __restrict__ zhi,
    __nv_bfloat16* __restrict__ zlo, int writeZ, int layer)
{
    __shared__ __nv_bfloat16 S[15360];
    const uint32_t sb = smem_u32(S);
    const int t = threadIdx.x, lane = t & 31, w = t >> 5;
    const int wm = w >> 1, wn = w & 1;
    const int m0 = blockIdx.y * 128, n0 = blockIdx.x * 64;

    float acc[2][4][4];
#pragma unroll
    for (int i = 0; i < 2; ++i)
#pragma unroll
        for (int j = 0; j < 4; ++j)
#pragma unroll
            for (int q = 0; q < 4; ++q) acc[i][j][q] = 0.f;

    // staging offsets
    const int ar = t >> 1, ah2 = (t & 1) * 16;        // A: row, 16-elem half
    const size_t aSrc = (size_t)(m0 + ar) * 768 + ah2;
    const int aDst = ar * 40 + ah2;
    const int br = t >> 2, bs = (t & 3) * 8;          // B: row, 8-elem seg
    const size_t bSrc = (size_t)(n0 + br) * 768 + bs;
    const int bDst = br * 40 + bs;

    uint4 pa0, pa1, pa2, pa3, pb0, pb1;
    pa0 = *reinterpret_cast<const uint4*>(Zhi + aSrc);
    pa1 = *reinterpret_cast<const uint4*>(Zhi + aSrc + 8);
    pa2 = *reinterpret_cast<const uint4*>(Zlo + aSrc);
    pa3 = *reinterpret_cast<const uint4*>(Zlo + aSrc + 8);
    pb0 = *reinterpret_cast<const uint4*>(THh + bSrc);
    pb1 = *reinterpret_cast<const uint4*>(THl + bSrc);

    // ldmatrix addrs
    const uint32_t aAddr = sb + 2 * ((wm * 32 + (lane & 15)) * 40 + (lane >> 4) * 8);
    const uint32_t bAddr = sb + 2 * (10240 + (wn * 32 + (lane & 15)) * 40 + (lane >> 4) * 8);

    for (int c = 0; c < 24; ++c) {
        __syncthreads();
        *reinterpret_cast<uint4*>(&S[aDst])        = pa0;
        *reinterpret_cast<uint4*>(&S[aDst + 8])    = pa1;
        *reinterpret_cast<uint4*>(&S[5120 + aDst]) = pa2;
        *reinterpret_cast<uint4*>(&S[5120 + aDst + 8]) = pa3;
        *reinterpret_cast<uint4*>(&S[10240 + bDst]) = pb0;
        *reinterpret_cast<uint4*>(&S[12800 + bDst]) = pb1;
        if (c < 23) {
            size_t ka = aSrc + (c + 1) * 32, kb = bSrc + (c + 1) * 32;
            pa0 = *reinterpret_cast<const uint4*>(Zhi + ka);
            pa1 = *reinterpret_cast<const uint4*>(Zhi + ka + 8);
            pa2 = *reinterpret_cast<const uint4*>(Zlo + ka);
            pa3 = *reinterpret_cast<const uint4*>(Zlo + ka + 8);
            pb0 = *reinterpret_cast<const uint4*>(THh + kb);
            pb1 = *reinterpret_cast<const uint4*>(THl + kb);
        }
        __syncthreads();

#pragma unroll
        for (int ks = 0; ks < 2; ++ks) {
            uint32_t ahr[2][4], alr[2][4], bhr[2][4], blr[2][4];
#pragma unroll
            for (int mt = 0; mt < 2; ++mt) {
                uint32_t off = 2 * (mt * 16 * 40 + ks * 16);
                ldsm_x4(ahr[mt], aAddr + off);
                ldsm_x4(alr[mt], aAddr + 2 * 5120 + off);
            }
#pragma unroll
            for (int np = 0; np < 2; ++np) {
                uint32_t off = 2 * (np * 16 * 40 + ks * 16);
                ldsm_x4(bhr[np], bAddr + off);
                ldsm_x4(blr[np], bAddr + 2 * 2560 + off);
            }
#pragma unroll
            for (int mt = 0; mt < 2; ++mt)
#pragma unroll
                for (int nt = 0; nt < 4; ++nt) {
                    int np = nt >> 1, s = nt & 1;
                    mma_bf16(acc[mt][nt], ahr[mt], bhr[np][s], bhr[np][s + 2]);
                    mma_bf16(acc[mt][nt], ahr[mt], blr[np][s], blr[np][s + 2]);
                    mma_bf16(acc[mt][nt], alr[mt], bhr[np][s], bhr[np][s + 2]);
                }
        }
    }

    // epilogue: relu, write V (and h-split into Z cols 0..255)
#pragma unroll
    for (int mt = 0; mt < 2; ++mt)
#pragma unroll
        for (int nt = 0; nt < 4; ++nt) {
            int n = n0 + wn * 32 + nt * 8 + (lane & 3) * 2;
#pragma unroll
            for (int hf = 0; hf < 2; ++hf) {
                int m = m0 + wm * 32 + mt * 16 + (lane >> 2) + hf * 8;
                float v0 = fmaxf(acc[mt][nt][hf * 2],     0.f);
                float v1 = fmaxf(acc[mt][nt][hf * 2 + 1], 0.f);
                int b = m >> 6, nd = m & 63;
                float2 vv = make_float2(v0, v1);
                *reinterpret_cast<float2*>(
                    Vout + ((size_t)(b * NLAYER + layer) * 64 + nd) * 256 + n) = vv;
                if (writeZ) {
                    __nv_bfloat16 h0, l0, h1, l1;
                    bsplit(v0, h0, l0); bsplit(v1, h1, l1);
                    __nv_bfloat162 ph; ph.x = h0; ph.y = h1;
                    __nv_bfloat162 pl; pl.x = l0; pl.y = l1;
                    *reinterpret_cast<__nv_bfloat162*>(zhi + (size_t)m * 768 + n) = ph;
                    *reinterpret_cast<__nv_bfloat162*>(zlo + (size_t)m * 768 + n) = pl;
                }
            }
        }
}

// ---------------- launcher ----------------
extern "C" void kernel_launch(void* const* d_in, const int* in_sizes, int n_in,
                              void* d_out, int out_size)
{
    const float* x     = (const float*)d_in[0];
    const float* Wq    = (const float*)d_in[1];
    const float* bq    = (const float*)d_in[2];
    const float* Wk    = (const float*)d_in[3];
    const float* bk    = (const float*)d_in[4];
    const float* theta = (const float*)d_in[5];

    float* out  = (float*)d_out;
    float* Vout = out;
    float* Aout = out + VELEMS;

    __nv_bfloat16 *Zhi, *Zlo, *THhi, *THlo;
    float *Qb, *Kb;
    cudaGetSymbolAddress((void**)&Zhi, g_Zhi);
    cudaGetSymbolAddress((void**)&Zlo, g_Zlo);
    cudaGetSymbolAddress((void**)&THhi, g_THhi);
    cudaGetSymbolAddress((void**)&THlo, g_THlo);
    cudaGetSymbolAddress((void**)&Qb, g_Q);
    cudaGetSymbolAddress((void**)&Kb, g_K);

    cudaFuncSetAttribute(attn_k, cudaFuncAttributeMaxDynamicSharedMemorySize, 49152);
    cudaFuncSetAttribute(cheb_k, cudaFuncAttributeMaxDynamicSharedMemorySize, 147456);

    split_x_k<<<16384, 256>>>(x, Zhi, Zlo);
    prep_th_k<<<3072, 256>>>(theta, THhi, THlo);

    dim3 qkGrid(2, 512);
    gemm_qk<<<qkGrid, 256>>>(x, Wq, bq, Qb);
    gemm_qk<<<qkGrid, 256>>>(x, Wk, bk, Kb);

    attn_k<<<B_SZ, 256, 49152>>>(Qb, Kb, Aout);

    dim3 thGrid(4, 512);
    for (int l = 0; l < NLAYER; ++l) {
        const float* hbase;
        long hStride;
        if (l == 0) { hbase = x; hStride = 64 * 256; }
        else {
            hbase = Vout + (size_t)(l - 1) * 64 * 256;
            hStride = (long)NLAYER * 64 * 256;
        }
        cheb_k<<<B_SZ, 512, 147456>>>(Aout, hbase, hStride, Zhi, Zlo);
        theta_mma<<<thGrid, 256>>>(Zhi, Zlo,
                                   THhi + (size_t)l * 196608, THlo + (size_t)l * 196608,
                                   Vout, Zhi, Zlo, (l < 3) ? 1 : 0, l);
    }
}

// round 6
// speedup vs baseline: 1.6798x; 1.1282x over previous
#include <cuda_runtime.h>
#include <cuda_bf16.h>
#include <math.h>
#include <stdint.h>

typedef unsigned long long ull;

#define B_SZ   1024
#define NLAYER 4
#define MROWS  65536
#define VELEMS ((size_t)B_SZ * NLAYER * 64 * 256)

// ---------------- scratch (static device globals; no allocation) ----------------
__device__ __align__(16) __nv_bfloat16 g_Zhi[(size_t)MROWS * 768];
__device__ __align__(16) __nv_bfloat16 g_Zlo[(size_t)MROWS * 768];
__device__ __align__(16) float         g_Q[(size_t)MROWS * 256];
__device__ __align__(16) float         g_K[(size_t)MROWS * 256];
__device__ __align__(16) __nv_bfloat16 g_THhi[4 * 256 * 768];
__device__ __align__(16) __nv_bfloat16 g_THlo[4 * 256 * 768];

// ---------------- helpers ----------------
__device__ __forceinline__ uint32_t smem_u32(const void* p) {
    uint32_t a;
    asm("{ .reg .u64 t; cvta.to.shared.u64 t, %1; cvt.u32.u64 %0, t; }" : "=r"(a) : "l"(p));
    return a;
}
__device__ __forceinline__ void ldsm_x4(uint32_t* r, uint32_t a) {
    asm volatile("ldmatrix.sync.aligned.m8n8.x4.shared.b16 {%0,%1,%2,%3}, [%4];"
                 : "=r"(r[0]), "=r"(r[1]), "=r"(r[2]), "=r"(r[3]) : "r"(a));
}
__device__ __forceinline__ void mma_bf16(float* d, const uint32_t* a, uint32_t b0, uint32_t b1) {
    asm volatile("mma.sync.aligned.m16n8k16.row.col.f32.bf16.bf16.f32 "
                 "{%0,%1,%2,%3}, {%4,%5,%6,%7}, {%8,%9}, {%0,%1,%2,%3};"
                 : "+f"(d[0]), "+f"(d[1]), "+f"(d[2]), "+f"(d[3])
                 : "r"(a[0]), "r"(a[1]), "r"(a[2]), "r"(a[3]), "r"(b0), "r"(b1));
}
__device__ __forceinline__ ull ffma2(ull a, ull b, ull c) {
    ull d; asm("fma.rn.f32x2 %0, %1, %2, %3;" : "=l"(d) : "l"(a), "l"(b), "l"(c));
    return d;
}
__device__ __forceinline__ ull dup2(float x) {
    ull d; asm("mov.b64 %0, {%1, %1};" : "=l"(d) : "f"(x)); return d;
}
__device__ __forceinline__ void upk2(ull v, float& lo, float& hi) {
    asm("mov.b64 {%0, %1}, %2;" : "=f"(lo), "=f"(hi) : "l"(v));
}
__device__ __forceinline__ void bsplit(float v, __nv_bfloat16& h, __nv_bfloat16& l) {
    h = __float2bfloat16(v);
    l = __float2bfloat16(v - __bfloat162float(h));
}

// ---------------- prep kernels ----------------
__global__ __launch_bounds__(256) void split_x_k(
    const float* __restrict__ x, __nv_bfloat16* __restrict__ zhi,
    __nv_bfloat16* __restrict__ zlo)
{
    int e = blockIdx.x * 256 + threadIdx.x;
    int m = e >> 6, q = e & 63;
    float4 v = reinterpret_cast<const float4*>(x)[e];
    __nv_bfloat16 h0, l0, h1, l1, h2, l2, h3, l3;
    bsplit(v.x, h0, l0); bsplit(v.y, h1, l1);
    bsplit(v.z, h2, l2); bsplit(v.w, h3, l3);
    size_t o = (size_t)m * 768 + q * 4;
    __nv_bfloat162 a; a.x = h0; a.y = h1;
    __nv_bfloat162 b; b.x = h2; b.y = h3;
    __nv_bfloat162 c; c.x = l0; c.y = l1;
    __nv_bfloat162 d; d.x = l2; d.y = l3;
    reinterpret_cast<__nv_bfloat162*>(zhi + o)[0] = a;
    reinterpret_cast<__nv_bfloat162*>(zhi + o)[1] = b;
    reinterpret_cast<__nv_bfloat162*>(zlo + o)[0] = c;
    reinterpret_cast<__nv_bfloat162*>(zlo + o)[1] = d;
}

__global__ __launch_bounds__(256) void prep_th_k(
    const float* __restrict__ theta,
    __nv_bfloat16* __restrict__ thi, __nv_bfloat16* __restrict__ tlo)
{
    int idx = blockIdx.x * 256 + threadIdx.x;   // 786432 total
    int l = idx / 196608, rem = idx % 196608;
    int n = rem / 768, k = rem % 768;
    float v = theta[(size_t)l * 196608 + (size_t)k * 256 + n];
    __nv_bfloat16 h, lo; bsplit(v, h, lo);
    thi[(size_t)l * 196608 + (size_t)n * 768 + k] = h;
    tlo[(size_t)l * 196608 + (size_t)n * 768 + k] = lo;
}

// ---------------- QK projection GEMM (fp32 FFMA2, proven) ----------------
#define BKT 16

__global__ __launch_bounds__(256) void gemm_qk(
    const float* __restrict__ A, const float* __restrict__ Bm,
    const float* __restrict__ bias, float* __restrict__ C)
{
    __shared__ float As[BKT][128];
    __shared__ float Bs[BKT][128];

    const int tid = threadIdx.x;
    const int m0 = blockIdx.y * 128;
    const int n0 = blockIdx.x * 128;

    ull acc[8][4];
#pragma unroll
    for (int i = 0; i < 8; ++i)
#pragma unroll
        for (int j = 0; j < 4; ++j) acc[i][j] = 0ull;

    const int ty = tid >> 4, tx = tid & 15;

    for (int k0 = 0; k0 < 256; k0 += BKT) {
#pragma unroll
        for (int i = 0; i < 2; ++i) {
            int e = tid * 2 + i, m = e >> 2, kq = e & 3;
            float4 v = *reinterpret_cast<const float4*>(A + (size_t)(m0 + m) * 256 + k0 + kq * 4);
            As[kq * 4 + 0][m] = v.x; As[kq * 4 + 1][m] = v.y;
            As[kq * 4 + 2][m] = v.z; As[kq * 4 + 3][m] = v.w;
        }
#pragma unroll
        for (int i = 0; i < 2; ++i) {
            int e = tid * 2 + i, kk = e >> 5, nq = e & 31;
            float4 v = *reinterpret_cast<const float4*>(Bm + (size_t)(k0 + kk) * 256 + n0 + nq * 4);
            *reinterpret_cast<float4*>(&Bs[kk][nq * 4]) = v;
        }
        __syncthreads();
#pragma unroll
        for (int kk = 0; kk < BKT; ++kk) {
            float4 a0 = *reinterpret_cast<const float4*>(&As[kk][ty * 8]);
            float4 a1 = *reinterpret_cast<const float4*>(&As[kk][ty * 8 + 4]);
            ulonglong2 b0 = *reinterpret_cast<const ulonglong2*>(&Bs[kk][tx * 8]);
            ulonglong2 b1 = *reinterpret_cast<const ulonglong2*>(&Bs[kk][tx * 8 + 4]);
            float av[8] = {a0.x, a0.y, a0.z, a0.w, a1.x, a1.y, a1.z, a1.w};
#pragma unroll
            for (int i = 0; i < 8; ++i) {
                ull ad = dup2(av[i]);
                acc[i][0] = ffma2(ad, b0.x, acc[i][0]);
                acc[i][1] = ffma2(ad, b0.y, acc[i][1]);
                acc[i][2] = ffma2(ad, b1.x, acc[i][2]);
                acc[i][3] = ffma2(ad, b1.y, acc[i][3]);
            }
        }
        __syncthreads();
    }

    float bv[8];
#pragma unroll
    for (int j = 0; j < 8; ++j) bv[j] = bias[n0 + tx * 8 + j];
#pragma unroll
    for (int i = 0; i < 8; ++i) {
        int m = m0 + ty * 8 + i;
        float v[8];
#pragma unroll
        for (int j = 0; j < 4; ++j) upk2(acc[i][j], v[j * 2], v[j * 2 + 1]);
#pragma unroll
        for (int j = 0; j < 8; ++j) v[j] += bv[j];
        float4* p = reinterpret_cast<float4*>(C + (size_t)m * 256 + n0 + tx * 8);
        p[0] = make_float4(v[0], v[1], v[2], v[3]);
        p[1] = make_float4(v[4], v[5], v[6], v[7]);
    }
}

// ---------------- attention -> normalized adjacency (proven) ----------------
__global__ __launch_bounds__(256) void attn_k(
    const float* __restrict__ Q, const float* __restrict__ Kmat,
    float* __restrict__ Aout)
{
    extern __shared__ float sm[];
    float* qs  = sm;
    float* ks  = sm + 4096;
    float* adj = sm + 8192;
    __shared__ float deg[64];

    const int b = blockIdx.x, t = threadIdx.x;
    const int i = t >> 2, g = t & 3;

    for (int e = t; e < 4096; e += 256) adj[e] = 0.f;

    for (int h = 0; h < 4; ++h) {
        __syncthreads();
        for (int e = t; e < 4096; e += 256) {
            int n = e >> 6, d = e & 63;
            size_t base = ((size_t)b * 64 + n) * 256 + h * 64 + d;
            qs[e] = Q[base];
            ks[e] = Kmat[base];
        }
        __syncthreads();

        float s[16];
#pragma unroll
        for (int jj = 0; jj < 16; ++jj) s[jj] = 0.f;
        for (int d = 0; d < 64; ++d) {
            float qv = qs[i * 64 + d];
#pragma unroll
            for (int jj = 0; jj < 16; ++jj)
                s[jj] += qv * ks[(g * 16 + jj) * 64 + d];
        }
        float mx = -INFINITY;
#pragma unroll
        for (int jj = 0; jj < 16; ++jj) { s[jj] *= 1.25e8f; mx = fmaxf(mx, s[jj]); }
        mx = fmaxf(mx, __shfl_xor_sync(0xffffffffu, mx, 1));
        mx = fmaxf(mx, __shfl_xor_sync(0xffffffffu, mx, 2));
        float sum = 0.f;
#pragma unroll
        for (int jj = 0; jj < 16; ++jj) { s[jj] = __expf(s[jj] - mx); sum += s[jj]; }
        sum += __shfl_xor_sync(0xffffffffu, sum, 1);
        sum += __shfl_xor_sync(0xffffffffu, sum, 2);
        float inv = 0.25f / sum;
#pragma unroll
        for (int jj = 0; jj < 16; ++jj)
            adj[i * 64 + g * 16 + jj] += s[jj] * inv;
    }
    __syncthreads();

    float sv[16];
#pragma unroll
    for (int jj = 0; jj < 16; ++jj) {
        int j = g * 16 + jj;
        sv[jj] = 0.5f * (adj[i * 64 + j] + adj[j * 64 + i]);
    }
    __syncthreads();
#pragma unroll
    for (int jj = 0; jj < 16; ++jj) adj[i * 64 + g * 16 + jj] = sv[jj];

    float ds = 0.f;
#pragma unroll
    for (int jj = 0; jj < 16; ++jj) ds += sv[jj];
    ds += __shfl_xor_sync(0xffffffffu, ds, 1);
    ds += __shfl_xor_sync(0xffffffffu, ds, 2);
    if (g == 0) deg[i] = rsqrtf(ds);
    __syncthreads();

    float di = deg[i];
#pragma unroll
    for (int jj = 0; jj < 16; ++jj) {
        int j = g * 16 + jj;
        Aout[(size_t)b * 4096 + i * 64 + j] = di * adj[i * 64 + j] * deg[j];
    }
}

// ---------------- Chebyshev z1/z2 build, feature-split x2 ----------------
// grid (2, 1024): x = feature half (128 cols), y = batch. smem 80 KB -> 2 blocks/SM.
__global__ __launch_bounds__(512, 2) void cheb_k(
    const float* __restrict__ Aglob, const float* __restrict__ hbase, long hStride,
    __nv_bfloat16* __restrict__ zhi, __nv_bfloat16* __restrict__ zlo)
{
    extern __shared__ float sm[];
    float* Lt = sm;           // 64*64
    float* hs = sm + 4096;    // 64*128
    float* z1 = sm + 12288;   // 64*128

    const int b = blockIdx.y, f0 = blockIdx.x * 128;
    const int t = threadIdx.x;

    {
        const float4* Ab = reinterpret_cast<const float4*>(Aglob + (size_t)b * 4096);
        float4* Ld = reinterpret_cast<float4*>(Lt);
        for (int e = t; e < 1024; e += 512) {
            float4 v = Ab[e];
            Ld[e] = make_float4(-v.x, -v.y, -v.z, -v.w);
        }
        const float* hb = hbase + (size_t)b * hStride;
        for (int e = t; e < 2048; e += 512) {
            int r = e >> 5, q = e & 31;
            float4 v = *reinterpret_cast<const float4*>(hb + (size_t)r * 256 + f0 + q * 4);
            *reinterpret_cast<float4*>(hs + r * 128 + q * 4) = v;
        }
    }
    __syncthreads();

    const int fp = t & 63;      // feature pair within 128-col slice
    const int grp = t >> 6;     // 8 groups of 8 rows

    // ---- z1 = Lt @ h (slice) ----
    {
        ull acc[8];
#pragma unroll
        for (int p = 0; p < 8; ++p) acc[p] = 0ull;
        for (int j = 0; j < 64; j += 4) {
            ull h0 = *reinterpret_cast<const ull*>(&hs[(j + 0) * 128 + fp * 2]);
            ull h1 = *reinterpret_cast<const ull*>(&hs[(j + 1) * 128 + fp * 2]);
            ull h2 = *reinterpret_cast<const ull*>(&hs[(j + 2) * 128 + fp * 2]);
            ull h3 = *reinterpret_cast<const ull*>(&hs[(j + 3) * 128 + fp * 2]);
#pragma unroll
            for (int r = 0; r < 8; ++r) {
                float4 lt = *reinterpret_cast<const float4*>(&Lt[(grp * 8 + r) * 64 + j]);
                acc[r] = ffma2(dup2(lt.x), h0, acc[r]);
                acc[r] = ffma2(dup2(lt.y), h1, acc[r]);
                acc[r] = ffma2(dup2(lt.z), h2, acc[r]);
                acc[r] = ffma2(dup2(lt.w), h3, acc[r]);
            }
        }
#pragma unroll
        for (int r = 0; r < 8; ++r) {
            int row = grp * 8 + r;
            *reinterpret_cast<ull*>(&z1[row * 128 + fp * 2]) = acc[r];
            float lo_, hi_;
            upk2(acc[r], lo_, hi_);
            __nv_bfloat16 h0, l0, h1, l1;
            bsplit(lo_, h0, l0); bsplit(hi_, h1, l1);
            size_t zo = ((size_t)(b * 64 + row)) * 768 + 256 + f0 + fp * 2;
            __nv_bfloat162 ph; ph.x = h0; ph.y = h1;
            __nv_bfloat162 pl; pl.x = l0; pl.y = l1;
            *reinterpret_cast<__nv_bfloat162*>(zhi + zo) = ph;
            *reinterpret_cast<__nv_bfloat162*>(zlo + zo) = pl;
        }
    }
    __syncthreads();

    // ---- z2 = 2 * Lt @ z1 - h ----
    {
        ull acc[8];
#pragma unroll
        for (int p = 0; p < 8; ++p) acc[p] = 0ull;
        for (int j = 0; j < 64; j += 4) {
            ull h0 = *reinterpret_cast<const ull*>(&z1[(j + 0) * 128 + fp * 2]);
            ull h1 = *reinterpret_cast<const ull*>(&z1[(j + 1) * 128 + fp * 2]);
            ull h2 = *reinterpret_cast<const ull*>(&z1[(j + 2) * 128 + fp * 2]);
            ull h3 = *reinterpret_cast<const ull*>(&z1[(j + 3) * 128 + fp * 2]);
#pragma unroll
            for (int r = 0; r < 8; ++r) {
                float4 lt = *reinterpret_cast<const float4*>(&Lt[(grp * 8 + r) * 64 + j]);
                acc[r] = ffma2(dup2(lt.x), h0, acc[r]);
                acc[r] = ffma2(dup2(lt.y), h1, acc[r]);
                acc[r] = ffma2(dup2(lt.z), h2, acc[r]);
                acc[r] = ffma2(dup2(lt.w), h3, acc[r]);
            }
        }
#pragma unroll
        for (int r = 0; r < 8; ++r) {
            int row = grp * 8 + r;
            int idx = row * 128 + fp * 2;
            float lo_, hi_;
            upk2(acc[r], lo_, hi_);
            float v0 = 2.f * lo_ - hs[idx];
            float v1 = 2.f * hi_ - hs[idx + 1];
            __nv_bfloat16 h0, l0, h1, l1;
            bsplit(v0, h0, l0); bsplit(v1, h1, l1);
            size_t zo = ((size_t)(b * 64 + row)) * 768 + 512 + f0 + fp * 2;
            __nv_bfloat162 ph; ph.x = h0; ph.y = h1;
            __nv_bfloat162 pl; pl.x = l0; pl.y = l1;
            *reinterpret_cast<__nv_bfloat162*>(zhi + zo) = ph;
            *reinterpret_cast<__nv_bfloat162*>(zlo + zo) = pl;
        }
    }
}

// ---------------- theta GEMM: bf16x3 mma, tile M=128 N=128, 512 threads ----------------
// smem (bf16 elems): Ahi[0), Alo[5120), Bhi[10240), Blo[15360); rows padded to 40.
__global__ __launch_bounds__(512, 1) void theta_mma(
    const __nv_bfloat16* __restrict__ Zhi, const __nv_bfloat16* __restrict__ Zlo,
    const __nv_bfloat16* __restrict__ THh, const __nv_bfloat16* __restrict__ THl,
    float* __restrict__ Vout, __nv_bfloat16* __restrict__ zhi,
    __nv_bfloat16* __restrict__ zlo, int writeZ, int layer)
{
    __shared__ __nv_bfloat16 S[20480];
    const uint32_t sb = smem_u32(S);
    const int t = threadIdx.x, lane = t & 31, w = t >> 5;
    const int wm = w >> 2, wn = w & 3;
    const int m0 = blockIdx.y * 128, n0 = blockIdx.x * 128;

    float acc[2][4][4];
#pragma unroll
    for (int i = 0; i < 2; ++i)
#pragma unroll
        for (int j = 0; j < 4; ++j)
#pragma unroll
            for (int q = 0; q < 4; ++q) acc[i][j][q] = 0.f;

    // staging: each thread 1 uint4 per array; rows 0..127, 8-elem segs
    const int ar = t >> 2, as = (t & 3) * 8;
    const size_t aSrc = (size_t)(m0 + ar) * 768 + as;
    const size_t bSrc = (size_t)(n0 + ar) * 768 + as;
    const int dOff = ar * 40 + as;

    uint4 pa0, pa1, pb0, pb1;
    pa0 = *reinterpret_cast<const uint4*>(Zhi + aSrc);
    pa1 = *reinterpret_cast<const uint4*>(Zlo + aSrc);
    pb0 = *reinterpret_cast<const uint4*>(THh + bSrc);
    pb1 = *reinterpret_cast<const uint4*>(THl + bSrc);

    const uint32_t aAddr = sb + 2 * ((wm * 32 + (lane & 15)) * 40 + (lane >> 4) * 8);
    const uint32_t bAddr = sb + 2 * (10240 + (wn * 32 + (lane & 15)) * 40 + (lane >> 4) * 8);

    for (int c = 0; c < 24; ++c) {
        __syncthreads();
        *reinterpret_cast<uint4*>(&S[dOff])         = pa0;
        *reinterpret_cast<uint4*>(&S[5120 + dOff])  = pa1;
        *reinterpret_cast<uint4*>(&S[10240 + dOff]) = pb0;
        *reinterpret_cast<uint4*>(&S[15360 + dOff]) = pb1;
        if (c < 23) {
            size_t ka = aSrc + (c + 1) * 32, kb = bSrc + (c + 1) * 32;
            pa0 = *reinterpret_cast<const uint4*>(Zhi + ka);
            pa1 = *reinterpret_cast<const uint4*>(Zlo + ka);
            pb0 = *reinterpret_cast<const uint4*>(THh + kb);
            pb1 = *reinterpret_cast<const uint4*>(THl + kb);
        }
        __syncthreads();

#pragma unroll
        for (int ks = 0; ks < 2; ++ks) {
            uint32_t ahr[2][4], alr[2][4], bhr[2][4], blr[2][4];
#pragma unroll
            for (int mt = 0; mt < 2; ++mt) {
                uint32_t off = 2 * (mt * 16 * 40 + ks * 16);
                ldsm_x4(ahr[mt], aAddr + off);
                ldsm_x4(alr[mt], aAddr + 2 * 5120 + off);
            }
#pragma unroll
            for (int np = 0; np < 2; ++np) {
                uint32_t off = 2 * (np * 16 * 40 + ks * 16);
                ldsm_x4(bhr[np], bAddr + off);
                ldsm_x4(blr[np], bAddr + 2 * 5120 + off);
            }
#pragma unroll
            for (int mt = 0; mt < 2; ++mt)
#pragma unroll
                for (int nt = 0; nt < 4; ++nt) {
                    int np = nt >> 1, s = nt & 1;
                    mma_bf16(acc[mt][nt], ahr[mt], bhr[np][s], bhr[np][s + 2]);
                    mma_bf16(acc[mt][nt], ahr[mt], blr[np][s], blr[np][s + 2]);
                    mma_bf16(acc[mt][nt], alr[mt], bhr[np][s], bhr[np][s + 2]);
                }
        }
    }

    // epilogue
#pragma unroll
    for (int mt = 0; mt < 2; ++mt)
#pragma unroll
        for (int nt = 0; nt < 4; ++nt) {
            int np = nt >> 1, s = nt & 1;
            int n = n0 + wn * 32 + np * 16 + s * 8 + (lane & 3) * 2;
#pragma unroll
            for (int hf = 0; hf < 2; ++hf) {
                int m = m0 + wm * 32 + mt * 16 + (lane >> 2) + hf * 8;
                float v0 = fmaxf(acc[mt][nt][hf * 2],     0.f);
                float v1 = fmaxf(acc[mt][nt][hf * 2 + 1], 0.f);
                int b = m >> 6, nd = m & 63;
                float2 vv = make_float2(v0, v1);
                *reinterpret_cast<float2*>(
                    Vout + ((size_t)(b * NLAYER + layer) * 64 + nd) * 256 + n) = vv;
                if (writeZ) {
                    __nv_bfloat16 h0, l0, h1, l1;
                    bsplit(v0, h0, l0); bsplit(v1, h1, l1);
                    __nv_bfloat162 ph; ph.x = h0; ph.y = h1;
                    __nv_bfloat162 pl; pl.x = l0; pl.y = l1;
                    *reinterpret_cast<__nv_bfloat162*>(zhi + (size_t)m * 768 + n) = ph;
                    *reinterpret_cast<__nv_bfloat162*>(zlo + (size_t)m * 768 + n) = pl;
                }
            }
        }
}

// ---------------- launcher ----------------
extern "C" void kernel_launch(void* const* d_in, const int* in_sizes, int n_in,
                              void* d_out, int out_size)
{
    const float* x     = (const float*)d_in[0];
    const float* Wq    = (const float*)d_in[1];
    const float* bq    = (const float*)d_in[2];
    const float* Wk    = (const float*)d_in[3];
    const float* bk    = (const float*)d_in[4];
    const float* theta = (const float*)d_in[5];

    float* out  = (float*)d_out;
    float* Vout = out;
    float* Aout = out + VELEMS;

    __nv_bfloat16 *Zhi, *Zlo, *THhi, *THlo;
    float *Qb, *Kb;
    cudaGetSymbolAddress((void**)&Zhi, g_Zhi);
    cudaGetSymbolAddress((void**)&Zlo, g_Zlo);
    cudaGetSymbolAddress((void**)&THhi, g_THhi);
    cudaGetSymbolAddress((void**)&THlo, g_THlo);
    cudaGetSymbolAddress((void**)&Qb, g_Q);
    cudaGetSymbolAddress((void**)&Kb, g_K);

    cudaFuncSetAttribute(attn_k, cudaFuncAttributeMaxDynamicSharedMemorySize, 49152);
    cudaFuncSetAttribute(cheb_k, cudaFuncAttributeMaxDynamicSharedMemorySize, 81920);

    split_x_k<<<16384, 256>>>(x, Zhi, Zlo);
    prep_th_k<<<3072, 256>>>(theta, THhi, THlo);

    dim3 qkGrid(2, 512);
    gemm_qk<<<qkGrid, 256>>>(x, Wq, bq, Qb);
    gemm_qk<<<qkGrid, 256>>>(x, Wk, bk, Kb);

    attn_k<<<B_SZ, 256, 49152>>>(Qb, Kb, Aout);

    dim3 chGrid(2, B_SZ);
    dim3 thGrid(2, 512);
    for (int l = 0; l < NLAYER; ++l) {
        const float* hbase;
        long hStride;
        if (l == 0) { hbase = x; hStride = 64 * 256; }
        else {
            hbase = Vout + (size_t)(l - 1) * 64 * 256;
            hStride = (long)NLAYER * 64 * 256;
        }
        cheb_k<<<chGrid, 512, 81920>>>(Aout, hbase, hStride, Zhi, Zlo);
        theta_mma<<<thGrid, 512>>>(Zhi, Zlo,
                                   THhi + (size_t)l * 196608, THlo + (size_t)l * 196608,
                                   Vout, Zhi, Zlo, (l < 3) ? 1 : 0, l);
    }
}

// round 7
// speedup vs baseline: 1.7851x; 1.0627x over previous
#include <cuda_runtime.h>
#include <cuda_bf16.h>
#include <math.h>
#include <stdint.h>

typedef unsigned long long ull;

#define B_SZ   1024
#define NLAYER 4
#define MROWS  65536
#define VELEMS ((size_t)B_SZ * NLAYER * 64 * 256)

// ---------------- scratch (static device globals; no allocation) ----------------
__device__ __align__(16) __nv_bfloat16 g_Zhi[(size_t)MROWS * 768];
__device__ __align__(16) __nv_bfloat16 g_Zlo[(size_t)MROWS * 768];
__device__ __align__(16) float         g_Q[(size_t)MROWS * 256];
__device__ __align__(16) float         g_K[(size_t)MROWS * 256];
__device__ __align__(16) __nv_bfloat16 g_THhi[4 * 256 * 768];
__device__ __align__(16) __nv_bfloat16 g_THlo[4 * 256 * 768];

// ---------------- helpers ----------------
__device__ __forceinline__ uint32_t smem_u32(const void* p) {
    uint32_t a;
    asm("{ .reg .u64 t; cvta.to.shared.u64 t, %1; cvt.u32.u64 %0, t; }" : "=r"(a) : "l"(p));
    return a;
}
__device__ __forceinline__ void ldsm_x4(uint32_t* r, uint32_t a) {
    asm volatile("ldmatrix.sync.aligned.m8n8.x4.shared.b16 {%0,%1,%2,%3}, [%4];"
                 : "=r"(r[0]), "=r"(r[1]), "=r"(r[2]), "=r"(r[3]) : "r"(a));
}
__device__ __forceinline__ void ldsm_x4t(uint32_t* r, uint32_t a) {
    asm volatile("ldmatrix.sync.aligned.m8n8.x4.trans.shared.b16 {%0,%1,%2,%3}, [%4];"
                 : "=r"(r[0]), "=r"(r[1]), "=r"(r[2]), "=r"(r[3]) : "r"(a));
}
__device__ __forceinline__ void mma_bf16(float* d, const uint32_t* a, uint32_t b0, uint32_t b1) {
    asm volatile("mma.sync.aligned.m16n8k16.row.col.f32.bf16.bf16.f32 "
                 "{%0,%1,%2,%3}, {%4,%5,%6,%7}, {%8,%9}, {%0,%1,%2,%3};"
                 : "+f"(d[0]), "+f"(d[1]), "+f"(d[2]), "+f"(d[3])
                 : "r"(a[0]), "r"(a[1]), "r"(a[2]), "r"(a[3]), "r"(b0), "r"(b1));
}
__device__ __forceinline__ ull ffma2(ull a, ull b, ull c) {
    ull d; asm("fma.rn.f32x2 %0, %1, %2, %3;" : "=l"(d) : "l"(a), "l"(b), "l"(c));
    return d;
}
__device__ __forceinline__ ull dup2(float x) {
    ull d; asm("mov.b64 %0, {%1, %1};" : "=l"(d) : "f"(x)); return d;
}
__device__ __forceinline__ void upk2(ull v, float& lo, float& hi) {
    asm("mov.b64 {%0, %1}, %2;" : "=f"(lo), "=f"(hi) : "l"(v));
}
__device__ __forceinline__ void bsplit(float v, __nv_bfloat16& h, __nv_bfloat16& l) {
    h = __float2bfloat16(v);
    l = __float2bfloat16(v - __bfloat162float(h));
}

// ---------------- prep kernels ----------------
__global__ __launch_bounds__(256) void split_x_k(
    const float* __restrict__ x, __nv_bfloat16* __restrict__ zhi,
    __nv_bfloat16* __restrict__ zlo)
{
    int e = blockIdx.x * 256 + threadIdx.x;
    int m = e >> 6, q = e & 63;
    float4 v = reinterpret_cast<const float4*>(x)[e];
    __nv_bfloat16 h0, l0, h1, l1, h2, l2, h3, l3;
    bsplit(v.x, h0, l0); bsplit(v.y, h1, l1);
    bsplit(v.z, h2, l2); bsplit(v.w, h3, l3);
    size_t o = (size_t)m * 768 + q * 4;
    __nv_bfloat162 a; a.x = h0; a.y = h1;
    __nv_bfloat162 b; b.x = h2; b.y = h3;
    __nv_bfloat162 c; c.x = l0; c.y = l1;
    __nv_bfloat162 d; d.x = l2; d.y = l3;
    reinterpret_cast<__nv_bfloat162*>(zhi + o)[0] = a;
    reinterpret_cast<__nv_bfloat162*>(zhi + o)[1] = b;
    reinterpret_cast<__nv_bfloat162*>(zlo + o)[0] = c;
    reinterpret_cast<__nv_bfloat162*>(zlo + o)[1] = d;
}

__global__ __launch_bounds__(256) void prep_th_k(
    const float* __restrict__ theta,
    __nv_bfloat16* __restrict__ thi, __nv_bfloat16* __restrict__ tlo)
{
    int idx = blockIdx.x * 256 + threadIdx.x;   // 786432 total
    int l = idx / 196608, rem = idx % 196608;
    int n = rem / 768, k = rem % 768;
    float v = theta[(size_t)l * 196608 + (size_t)k * 256 + n];
    __nv_bfloat16 h, lo; bsplit(v, h, lo);
    thi[(size_t)l * 196608 + (size_t)n * 768 + k] = h;
    tlo[(size_t)l * 196608 + (size_t)n * 768 + k] = lo;
}

// ---------------- QK projection GEMM (fp32 FFMA2, proven) ----------------
#define BKT 16

__global__ __launch_bounds__(256) void gemm_qk(
    const float* __restrict__ A, const float* __restrict__ Bm,
    const float* __restrict__ bias, float* __restrict__ C)
{
    __shared__ float As[BKT][128];
    __shared__ float Bs[BKT][128];

    const int tid = threadIdx.x;
    const int m0 = blockIdx.y * 128;
    const int n0 = blockIdx.x * 128;

    ull acc[8][4];
#pragma unroll
    for (int i = 0; i < 8; ++i)
#pragma unroll
        for (int j = 0; j < 4; ++j) acc[i][j] = 0ull;

    const int ty = tid >> 4, tx = tid & 15;

    for (int k0 = 0; k0 < 256; k0 += BKT) {
#pragma unroll
        for (int i = 0; i < 2; ++i) {
            int e = tid * 2 + i, m = e >> 2, kq = e & 3;
            float4 v = *reinterpret_cast<const float4*>(A + (size_t)(m0 + m) * 256 + k0 + kq * 4);
            As[kq * 4 + 0][m] = v.x; As[kq * 4 + 1][m] = v.y;
            As[kq * 4 + 2][m] = v.z; As[kq * 4 + 3][m] = v.w;
        }
#pragma unroll
        for (int i = 0; i < 2; ++i) {
            int e = tid * 2 + i, kk = e >> 5, nq = e & 31;
            float4 v = *reinterpret_cast<const float4*>(Bm + (size_t)(k0 + kk) * 256 + n0 + nq * 4);
            *reinterpret_cast<float4*>(&Bs[kk][nq * 4]) = v;
        }
        __syncthreads();
#pragma unroll
        for (int kk = 0; kk < BKT; ++kk) {
            float4 a0 = *reinterpret_cast<const float4*>(&As[kk][ty * 8]);
            float4 a1 = *reinterpret_cast<const float4*>(&As[kk][ty * 8 + 4]);
            ulonglong2 b0 = *reinterpret_cast<const ulonglong2*>(&Bs[kk][tx * 8]);
            ulonglong2 b1 = *reinterpret_cast<const ulonglong2*>(&Bs[kk][tx * 8 + 4]);
            float av[8] = {a0.x, a0.y, a0.z, a0.w, a1.x, a1.y, a1.z, a1.w};
#pragma unroll
            for (int i = 0; i < 8; ++i) {
                ull ad = dup2(av[i]);
                acc[i][0] = ffma2(ad, b0.x, acc[i][0]);
                acc[i][1] = ffma2(ad, b0.y, acc[i][1]);
                acc[i][2] = ffma2(ad, b1.x, acc[i][2]);
                acc[i][3] = ffma2(ad, b1.y, acc[i][3]);
            }
        }
        __syncthreads();
    }

    float bv[8];
#pragma unroll
    for (int j = 0; j < 8; ++j) bv[j] = bias[n0 + tx * 8 + j];
#pragma unroll
    for (int i = 0; i < 8; ++i) {
        int m = m0 + ty * 8 + i;
        float v[8];
#pragma unroll
        for (int j = 0; j < 4; ++j) upk2(acc[i][j], v[j * 2], v[j * 2 + 1]);
#pragma unroll
        for (int j = 0; j < 8; ++j) v[j] += bv[j];
        float4* p = reinterpret_cast<float4*>(C + (size_t)m * 256 + n0 + tx * 8);
        p[0] = make_float4(v[0], v[1], v[2], v[3]);
        p[1] = make_float4(v[4], v[5], v[6], v[7]);
    }
}

// ---------------- attention -> normalized adjacency (proven) ----------------
__global__ __launch_bounds__(256) void attn_k(
    const float* __restrict__ Q, const float* __restrict__ Kmat,
    float* __restrict__ Aout)
{
    extern __shared__ float sm[];
    float* qs  = sm;
    float* ks  = sm + 4096;
    float* adj = sm + 8192;
    __shared__ float deg[64];

    const int b = blockIdx.x, t = threadIdx.x;
    const int i = t >> 2, g = t & 3;

    for (int e = t; e < 4096; e += 256) adj[e] = 0.f;

    for (int h = 0; h < 4; ++h) {
        __syncthreads();
        for (int e = t; e < 4096; e += 256) {
            int n = e >> 6, d = e & 63;
            size_t base = ((size_t)b * 64 + n) * 256 + h * 64 + d;
            qs[e] = Q[base];
            ks[e] = Kmat[base];
        }
        __syncthreads();

        float s[16];
#pragma unroll
        for (int jj = 0; jj < 16; ++jj) s[jj] = 0.f;
        for (int d = 0; d < 64; ++d) {
            float qv = qs[i * 64 + d];
#pragma unroll
            for (int jj = 0; jj < 16; ++jj)
                s[jj] += qv * ks[(g * 16 + jj) * 64 + d];
        }
        float mx = -INFINITY;
#pragma unroll
        for (int jj = 0; jj < 16; ++jj) { s[jj] *= 1.25e8f; mx = fmaxf(mx, s[jj]); }
        mx = fmaxf(mx, __shfl_xor_sync(0xffffffffu, mx, 1));
        mx = fmaxf(mx, __shfl_xor_sync(0xffffffffu, mx, 2));
        float sum = 0.f;
#pragma unroll
        for (int jj = 0; jj < 16; ++jj) { s[jj] = __expf(s[jj] - mx); sum += s[jj]; }
        sum += __shfl_xor_sync(0xffffffffu, sum, 1);
        sum += __shfl_xor_sync(0xffffffffu, sum, 2);
        float inv = 0.25f / sum;
#pragma unroll
        for (int jj = 0; jj < 16; ++jj)
            adj[i * 64 + g * 16 + jj] += s[jj] * inv;
    }
    __syncthreads();

    float sv[16];
#pragma unroll
    for (int jj = 0; jj < 16; ++jj) {
        int j = g * 16 + jj;
        sv[jj] = 0.5f * (adj[i * 64 + j] + adj[j * 64 + i]);
    }
    __syncthreads();
#pragma unroll
    for (int jj = 0; jj < 16; ++jj) adj[i * 64 + g * 16 + jj] = sv[jj];

    float ds = 0.f;
#pragma unroll
    for (int jj = 0; jj < 16; ++jj) ds += sv[jj];
    ds += __shfl_xor_sync(0xffffffffu, ds, 1);
    ds += __shfl_xor_sync(0xffffffffu, ds, 2);
    if (g == 0) deg[i] = rsqrtf(ds);
    __syncthreads();

    float di = deg[i];
#pragma unroll
    for (int jj = 0; jj < 16; ++jj) {
        int j = g * 16 + jj;
        Aout[(size_t)b * 4096 + i * 64 + j] = di * adj[i * 64 + j] * deg[j];
    }
}

// ---------------- Chebyshev z-build on tensor cores (bf16x3 mma) ----------------
// grid (2, 1024): feature half x batch. 256 thr = 8 warps (wm 0..1, wn 0..3).
// smem bf16 elem offsets (rows padded: Lt->72, h/z1->136):
#define LTH 0
#define LTL 4608
#define CHH 9216
#define CHL 17920
#define Z1H 26624
#define Z1L 35328
#define CHEB_SMEM (44032 * 2)

__device__ __forceinline__ void cheb_step(
    uint32_t sb, int wm, int wn, int lane, int srcH, int srcL, float acc[2][4][4])
{
#pragma unroll
    for (int i = 0; i < 2; ++i)
#pragma unroll
        for (int j = 0; j < 4; ++j)
#pragma unroll
            for (int q = 0; q < 4; ++q) acc[i][j][q] = 0.f;

#pragma unroll
    for (int ks = 0; ks < 4; ++ks) {
        uint32_t ahr[2][4], alr[2][4];
#pragma unroll
        for (int mt = 0; mt < 2; ++mt) {
            uint32_t ao = sb + 2 * ((wm * 32 + mt * 16 + (lane & 15)) * 72
                                    + ks * 16 + (lane >> 4) * 8);
            ldsm_x4(ahr[mt], ao + 2 * LTH);
            ldsm_x4(alr[mt], ao + 2 * LTL);
        }
        uint32_t bh[2][4], bl[2][4];
#pragma unroll
        for (int np = 0; np < 2; ++np) {
            uint32_t bo = sb + 2 * ((ks * 16 + (lane & 15)) * 136
                                    + wn * 32 + np * 16 + (lane >> 4) * 8);
            ldsm_x4t(bh[np], bo + 2 * srcH);
            ldsm_x4t(bl[np], bo + 2 * srcL);
        }
#pragma unroll
        for (int mt = 0; mt < 2; ++mt)
#pragma unroll
            for (int np = 0; np < 2; ++np)
#pragma unroll
                for (int s = 0; s < 2; ++s) {
                    int nt = np * 2 + s;
                    mma_bf16(acc[mt][nt], ahr[mt], bh[np][2 * s], bh[np][2 * s + 1]);
                    mma_bf16(acc[mt][nt], ahr[mt], bl[np][2 * s], bl[np][2 * s + 1]);
                    mma_bf16(acc[mt][nt], alr[mt], bh[np][2 * s], bh[np][2 * s + 1]);
                }
    }
}

__global__ __launch_bounds__(256, 2) void cheb_mma(
    const float* __restrict__ Aglob,
    __nv_bfloat16* __restrict__ zhi, __nv_bfloat16* __restrict__ zlo)
{
    extern __shared__ __nv_bfloat16 S[];
    const uint32_t sb = smem_u32(S);
    const int b = blockIdx.y, f0 = blockIdx.x * 128;
    const int t = threadIdx.x, lane = t & 31, w = t >> 5;
    const int wm = w >> 2, wn = w & 3;

    // Lt = -A[b], split hi/lo into smem
    {
        const float4* Ab = reinterpret_cast<const float4*>(Aglob + (size_t)b * 4096);
#pragma unroll
        for (int i = 0; i < 4; ++i) {
            int e = i * 256 + t;
            int r = e >> 4, q = (e & 15) * 4;
            float4 v = Ab[e];
            float vv[4] = {-v.x, -v.y, -v.z, -v.w};
            __nv_bfloat16 hh[4], ll[4];
#pragma unroll
            for (int j = 0; j < 4; ++j) bsplit(vv[j], hh[j], ll[j]);
            __nv_bfloat162 p0; p0.x = hh[0]; p0.y = hh[1];
            __nv_bfloat162 p1; p1.x = hh[2]; p1.y = hh[3];
            __nv_bfloat162 q0; q0.x = ll[0]; q0.y = ll[1];
            __nv_bfloat162 q1; q1.x = ll[2]; q1.y = ll[3];
            *reinterpret_cast<__nv_bfloat162*>(&S[LTH + r * 72 + q])     = p0;
            *reinterpret_cast<__nv_bfloat162*>(&S[LTH + r * 72 + q + 2]) = p1;
            *reinterpret_cast<__nv_bfloat162*>(&S[LTL + r * 72 + q])     = q0;
            *reinterpret_cast<__nv_bfloat162*>(&S[LTL + r * 72 + q + 2]) = q1;
        }
    }
    // h slice (already split in Z cols 0..255)
    {
#pragma unroll
        for (int i = 0; i < 4; ++i) {
            int e = i * 256 + t;
            int r = e >> 4, q = (e & 15) * 8;
            size_t src = (size_t)(b * 64 + r) * 768 + f0 + q;
            *reinterpret_cast<uint4*>(&S[CHH + r * 136 + q]) =
                *reinterpret_cast<const uint4*>(zhi + src);
            *reinterpret_cast<uint4*>(&S[CHL + r * 136 + q]) =
                *reinterpret_cast<const uint4*>(zlo + src);
        }
    }
    __syncthreads();

    float acc[2][4][4];

    // ---- z1 = Lt @ h ----
    cheb_step(sb, wm, wn, lane, CHH, CHL, acc);
#pragma unroll
    for (int mt = 0; mt < 2; ++mt)
#pragma unroll
        for (int nt = 0; nt < 4; ++nt) {
            int col = wn * 32 + nt * 8 + (lane & 3) * 2;
#pragma unroll
            for (int hf = 0; hf < 2; ++hf) {
                int row = wm * 32 + mt * 16 + (lane >> 2) + hf * 8;
                float v0 = acc[mt][nt][hf * 2], v1 = acc[mt][nt][hf * 2 + 1];
                __nv_bfloat16 h0, l0, h1, l1;
                bsplit(v0, h0, l0); bsplit(v1, h1, l1);
                __nv_bfloat162 ph; ph.x = h0; ph.y = h1;
                __nv_bfloat162 pl; pl.x = l0; pl.y = l1;
                *reinterpret_cast<__nv_bfloat162*>(&S[Z1H + row * 136 + col]) = ph;
                *reinterpret_cast<__nv_bfloat162*>(&S[Z1L + row * 136 + col]) = pl;
                size_t zo = (size_t)(b * 64 + row) * 768 + 256 + f0 + col;
                *reinterpret_cast<__nv_bfloat162*>(zhi + zo) = ph;
                *reinterpret_cast<__nv_bfloat162*>(zlo + zo) = pl;
            }
        }
    __syncthreads();

    // ---- z2 = 2 * Lt @ z1 - h ----
    cheb_step(sb, wm, wn, lane, Z1H, Z1L, acc);
#pragma unroll
    for (int mt = 0; mt < 2; ++mt)
#pragma unroll
        for (int nt = 0; nt < 4; ++nt) {
            int col = wn * 32 + nt * 8 + (lane & 3) * 2;
#pragma unroll
            for (int hf = 0; hf < 2; ++hf) {
                int row = wm * 32 + mt * 16 + (lane >> 2) + hf * 8;
                __nv_bfloat162 hh = *reinterpret_cast<const __nv_bfloat162*>(&S[CHH + row * 136 + col]);
                __nv_bfloat162 hl = *reinterpret_cast<const __nv_bfloat162*>(&S[CHL + row * 136 + col]);
                float b0 = __bfloat162float(hh.x) + __bfloat162float(hl.x);
                float b1 = __bfloat162float(hh.y) + __bfloat162float(hl.y);
                float v0 = 2.f * acc[mt][nt][hf * 2]     - b0;
                float v1 = 2.f * acc[mt][nt][hf * 2 + 1] - b1;
                __nv_bfloat16 h0, l0, h1, l1;
                bsplit(v0, h0, l0); bsplit(v1, h1, l1);
                __nv_bfloat162 ph; ph.x = h0; ph.y = h1;
                __nv_bfloat162 pl; pl.x = l0; pl.y = l1;
                size_t zo = (size_t)(b * 64 + row) * 768 + 512 + f0 + col;
                *reinterpret_cast<__nv_bfloat162*>(zhi + zo) = ph;
                *reinterpret_cast<__nv_bfloat162*>(zlo + zo) = pl;
            }
        }
}

// ---------------- theta GEMM: bf16x3 mma, tile M=128 N=128, 512 threads (proven) ----------------
__global__ __launch_bounds__(512, 1) void theta_mma(
    const __nv_bfloat16* __restrict__ Zhi, const __nv_bfloat16* __restrict__ Zlo,
    const __nv_bfloat16* __restrict__ THh, const __nv_bfloat16* __restrict__ THl,
    float* __restrict__ Vout, __nv_bfloat16* __restrict__ zhi,
    __nv_bfloat16* __restrict__ zlo, int writeZ, int layer)
{
    __shared__ __nv_bfloat16 S[20480];
    const uint32_t sb = smem_u32(S);
    const int t = threadIdx.x, lane = t & 31, w = t >> 5;
    const int wm = w >> 2, wn = w & 3;
    const int m0 = blockIdx.y * 128, n0 = blockIdx.x * 128;

    float acc[2][4][4];
#pragma unroll
    for (int i = 0; i < 2; ++i)
#pragma unroll
        for (int j = 0; j < 4; ++j)
#pragma unroll
            for (int q = 0; q < 4; ++q) acc[i][j][q] = 0.f;

    const int ar = t >> 2, as = (t & 3) * 8;
    const size_t aSrc = (size_t)(m0 + ar) * 768 + as;
    const size_t bSrc = (size_t)(n0 + ar) * 768 + as;
    const int dOff = ar * 40 + as;

    uint4 pa0, pa1, pb0, pb1;
    pa0 = *reinterpret_cast<const uint4*>(Zhi + aSrc);
    pa1 = *reinterpret_cast<const uint4*>(Zlo + aSrc);
    pb0 = *reinterpret_cast<const uint4*>(THh + bSrc);
    pb1 = *reinterpret_cast<const uint4*>(THl + bSrc);

    const uint32_t aAddr = sb + 2 * ((wm * 32 + (lane & 15)) * 40 + (lane >> 4) * 8);
    const uint32_t bAddr = sb + 2 * (10240 + (wn * 32 + (lane & 15)) * 40 + (lane >> 4) * 8);

    for (int c = 0; c < 24; ++c) {
        __syncthreads();
        *reinterpret_cast<uint4*>(&S[dOff])         = pa0;
        *reinterpret_cast<uint4*>(&S[5120 + dOff])  = pa1;
        *reinterpret_cast<uint4*>(&S[10240 + dOff]) = pb0;
        *reinterpret_cast<uint4*>(&S[15360 + dOff]) = pb1;
        if (c < 23) {
            size_t ka = aSrc + (c + 1) * 32, kb = bSrc + (c + 1) * 32;
            pa0 = *reinterpret_cast<const uint4*>(Zhi + ka);
            pa1 = *reinterpret_cast<const uint4*>(Zlo + ka);
            pb0 = *reinterpret_cast<const uint4*>(THh + kb);
            pb1 = *reinterpret_cast<const uint4*>(THl + kb);
        }
        __syncthreads();

#pragma unroll
        for (int ks = 0; ks < 2; ++ks) {
            uint32_t ahr[2][4], alr[2][4], bhr[2][4], blr[2][4];
#pragma unroll
            for (int mt = 0; mt < 2; ++mt) {
                uint32_t off = 2 * (mt * 16 * 40 + ks * 16);
                ldsm_x4(ahr[mt], aAddr + off);
                ldsm_x4(alr[mt], aAddr + 2 * 5120 + off);
            }
#pragma unroll
            for (int np = 0; np < 2; ++np) {
                uint32_t off = 2 * (np * 16 * 40 + ks * 16);
                ldsm_x4(bhr[np], bAddr + off);
                ldsm_x4(blr[np], bAddr + 2 * 5120 + off);
            }
#pragma unroll
            for (int mt = 0; mt < 2; ++mt)
#pragma unroll
                for (int nt = 0; nt < 4; ++nt) {
                    int np = nt >> 1, s = nt & 1;
                    mma_bf16(acc[mt][nt], ahr[mt], bhr[np][s], bhr[np][s + 2]);
                    mma_bf16(acc[mt][nt], ahr[mt], blr[np][s], blr[np][s + 2]);
                    mma_bf16(acc[mt][nt], alr[mt], bhr[np][s], bhr[np][s + 2]);
                }
        }
    }

#pragma unroll
    for (int mt = 0; mt < 2; ++mt)
#pragma unroll
        for (int nt = 0; nt < 4; ++nt) {
            int np = nt >> 1, s = nt & 1;
            int n = n0 + wn * 32 + np * 16 + s * 8 + (lane & 3) * 2;
#pragma unroll
            for (int hf = 0; hf < 2; ++hf) {
                int m = m0 + wm * 32 + mt * 16 + (lane >> 2) + hf * 8;
                float v0 = fmaxf(acc[mt][nt][hf * 2],     0.f);
                float v1 = fmaxf(acc[mt][nt][hf * 2 + 1], 0.f);
                int b = m >> 6, nd = m & 63;
                float2 vv = make_float2(v0, v1);
                *reinterpret_cast<float2*>(
                    Vout + ((size_t)(b * NLAYER + layer) * 64 + nd) * 256 + n) = vv;
                if (writeZ) {
                    __nv_bfloat16 h0, l0, h1, l1;
                    bsplit(v0, h0, l0); bsplit(v1, h1, l1);
                    __nv_bfloat162 ph; ph.x = h0; ph.y = h1;
                    __nv_bfloat162 pl; pl.x = l0; pl.y = l1;
                    *reinterpret_cast<__nv_bfloat162*>(zhi + (size_t)m * 768 + n) = ph;
                    *reinterpret_cast<__nv_bfloat162*>(zlo + (size_t)m * 768 + n) = pl;
                }
            }
        }
}

// ---------------- launcher ----------------
extern "C" void kernel_launch(void* const* d_in, const int* in_sizes, int n_in,
                              void* d_out, int out_size)
{
    const float* x     = (const float*)d_in[0];
    const float* Wq    = (const float*)d_in[1];
    const float* bq    = (const float*)d_in[2];
    const float* Wk    = (const float*)d_in[3];
    const float* bk    = (const float*)d_in[4];
    const float* theta = (const float*)d_in[5];

    float* out  = (float*)d_out;
    float* Vout = out;
    float* Aout = out + VELEMS;

    __nv_bfloat16 *Zhi, *Zlo, *THhi, *THlo;
    float *Qb, *Kb;
    cudaGetSymbolAddress((void**)&Zhi, g_Zhi);
    cudaGetSymbolAddress((void**)&Zlo, g_Zlo);
    cudaGetSymbolAddress((void**)&THhi, g_THhi);
    cudaGetSymbolAddress((void**)&THlo, g_THlo);
    cudaGetSymbolAddress((void**)&Qb, g_Q);
    cudaGetSymbolAddress((void**)&Kb, g_K);

    cudaFuncSetAttribute(attn_k, cudaFuncAttributeMaxDynamicSharedMemorySize, 49152);
    cudaFuncSetAttribute(cheb_mma, cudaFuncAttributeMaxDynamicSharedMemorySize, CHEB_SMEM);

    split_x_k<<<16384, 256>>>(x, Zhi, Zlo);
    prep_th_k<<<3072, 256>>>(theta, THhi, THlo);

    dim3 qkGrid(2, 512);
    gemm_qk<<<qkGrid, 256>>>(x, Wq, bq, Qb);
    gemm_qk<<<qkGrid, 256>>>(x, Wk, bk, Kb);

    attn_k<<<B_SZ, 256, 49152>>>(Qb, Kb, Aout);

    dim3 chGrid(2, B_SZ);
    dim3 thGrid(2, 512);
    for (int l = 0; l < NLAYER; ++l) {
        cheb_mma<<<chGrid, 256, CHEB_SMEM>>>(Aout, Zhi, Zlo);
        theta_mma<<<thGrid, 512>>>(Zhi, Zlo,
                                   THhi + (size_t)l * 196608, THlo + (size_t)l * 196608,
                                   Vout, Zhi, Zlo, (l < 3) ? 1 : 0, l);
    }
}

// round 8
// speedup vs baseline: 2.0920x; 1.1719x over previous
#include <cuda_runtime.h>
#include <cuda_bf16.h>
#include <math.h>
#include <stdint.h>

typedef unsigned long long ull;

#define B_SZ   1024
#define NLAYER 4
#define MROWS  65536
#define VELEMS ((size_t)B_SZ * NLAYER * 64 * 256)

// ---------------- scratch (static device globals; no allocation) ----------------
__device__ __align__(16) __nv_bfloat16 g_Zhi[(size_t)MROWS * 768];
__device__ __align__(16) __nv_bfloat16 g_Zlo[(size_t)MROWS * 768];
__device__ __align__(16) float         g_Q[(size_t)MROWS * 256];
__device__ __align__(16) float         g_K[(size_t)MROWS * 256];
__device__ __align__(16) float         g_Wt[2 * 256 * 256];
__device__ __align__(16) __nv_bfloat16 g_THhi[4 * 256 * 768];
__device__ __align__(16) __nv_bfloat16 g_THlo[4 * 256 * 768];

// ---------------- helpers ----------------
__device__ __forceinline__ uint32_t smem_u32(const void* p) {
    uint32_t a;
    asm("{ .reg .u64 t; cvta.to.shared.u64 t, %1; cvt.u32.u64 %0, t; }" : "=r"(a) : "l"(p));
    return a;
}
__device__ __forceinline__ void ldsm_x4(uint32_t* r, uint32_t a) {
    asm volatile("ldmatrix.sync.aligned.m8n8.x4.shared.b16 {%0,%1,%2,%3}, [%4];"
                 : "=r"(r[0]), "=r"(r[1]), "=r"(r[2]), "=r"(r[3]) : "r"(a));
}
__device__ __forceinline__ void ldsm_x4t(uint32_t* r, uint32_t a) {
    asm volatile("ldmatrix.sync.aligned.m8n8.x4.trans.shared.b16 {%0,%1,%2,%3}, [%4];"
                 : "=r"(r[0]), "=r"(r[1]), "=r"(r[2]), "=r"(r[3]) : "r"(a));
}
__device__ __forceinline__ void mma_bf16(float* d, const uint32_t* a, uint32_t b0, uint32_t b1) {
    asm volatile("mma.sync.aligned.m16n8k16.row.col.f32.bf16.bf16.f32 "
                 "{%0,%1,%2,%3}, {%4,%5,%6,%7}, {%8,%9}, {%0,%1,%2,%3};"
                 : "+f"(d[0]), "+f"(d[1]), "+f"(d[2]), "+f"(d[3])
                 : "r"(a[0]), "r"(a[1]), "r"(a[2]), "r"(a[3]), "r"(b0), "r"(b1));
}
__device__ __forceinline__ void mma_tf32(float* d, const uint32_t* a, uint32_t b0, uint32_t b1) {
    asm volatile("mma.sync.aligned.m16n8k8.row.col.f32.tf32.tf32.f32 "
                 "{%0,%1,%2,%3}, {%4,%5,%6,%7}, {%8,%9}, {%0,%1,%2,%3};"
                 : "+f"(d[0]), "+f"(d[1]), "+f"(d[2]), "+f"(d[3])
                 : "r"(a[0]), "r"(a[1]), "r"(a[2]), "r"(a[3]), "r"(b0), "r"(b1));
}
__device__ __forceinline__ uint32_t f2tf32(float f) {
    uint32_t r; asm("cvt.rna.tf32.f32 %0, %1;" : "=r"(r) : "f"(f)); return r;
}
__device__ __forceinline__ void bsplit(float v, __nv_bfloat16& h, __nv_bfloat16& l) {
    h = __float2bfloat16(v);
    l = __float2bfloat16(v - __bfloat162float(h));
}

// ---------------- prep kernels ----------------
__global__ __launch_bounds__(256) void split_x_k(
    const float* __restrict__ x, __nv_bfloat16* __restrict__ zhi,
    __nv_bfloat16* __restrict__ zlo)
{
    int e = blockIdx.x * 256 + threadIdx.x;
    int m = e >> 6, q = e & 63;
    float4 v = reinterpret_cast<const float4*>(x)[e];
    __nv_bfloat16 h0, l0, h1, l1, h2, l2, h3, l3;
    bsplit(v.x, h0, l0); bsplit(v.y, h1, l1);
    bsplit(v.z, h2, l2); bsplit(v.w, h3, l3);
    size_t o = (size_t)m * 768 + q * 4;
    __nv_bfloat162 a; a.x = h0; a.y = h1;
    __nv_bfloat162 b; b.x = h2; b.y = h3;
    __nv_bfloat162 c; c.x = l0; c.y = l1;
    __nv_bfloat162 d; d.x = l2; d.y = l3;
    reinterpret_cast<__nv_bfloat162*>(zhi + o)[0] = a;
    reinterpret_cast<__nv_bfloat162*>(zhi + o)[1] = b;
    reinterpret_cast<__nv_bfloat162*>(zlo + o)[0] = c;
    reinterpret_cast<__nv_bfloat162*>(zlo + o)[1] = d;
}

__global__ __launch_bounds__(256) void prep_wt_k(
    const float* __restrict__ Wq, const float* __restrict__ Wk, float* __restrict__ Wt)
{
    int i = blockIdx.x * 256 + threadIdx.x;   // 131072
    int mat = i >> 16, rem = i & 65535;
    int n = rem >> 8, k = rem & 255;
    Wt[i] = (mat ? Wk : Wq)[k * 256 + n];
}

__global__ __launch_bounds__(256) void prep_th_k(
    const float* __restrict__ theta,
    __nv_bfloat16* __restrict__ thi, __nv_bfloat16* __restrict__ tlo)
{
    int idx = blockIdx.x * 256 + threadIdx.x;   // 786432 total
    int l = idx / 196608, rem = idx % 196608;
    int n = rem / 768, k = rem % 768;
    float v = theta[(size_t)l * 196608 + (size_t)k * 256 + n];
    __nv_bfloat16 h, lo; bsplit(v, h, lo);
    thi[(size_t)l * 196608 + (size_t)n * 768 + k] = h;
    tlo[(size_t)l * 196608 + (size_t)n * 768 + k] = lo;
}

// ---------------- QK projection: 3xTF32 mma ----------------
// C(65536x256) = X @ W + b. Wt = W^T ([n][k]). Tile M=128 N=128 Kc=32 (8 chunks).
// 256 thr = 8 warps (wm 0..1 x wn 0..3), warp tile 64x32.
// dyn smem floats: xs_h[0), xs_l[4608), ws_h[9216), ws_l[13824); rows padded to 36.
#define QK_SMEM (18432 * 4)

__global__ __launch_bounds__(256, 2) void qk_tf32(
    const float* __restrict__ X, const float* __restrict__ Wt,
    const float* __restrict__ bias, float* __restrict__ C)
{
    extern __shared__ float sm[];
    float* xs_h = sm;
    float* xs_l = sm + 4608;
    float* ws_h = sm + 9216;
    float* ws_l = sm + 13824;

    const int t = threadIdx.x, lane = t & 31, w = t >> 5;
    const int wm = w >> 2, wn = w & 3;
    const int m0 = blockIdx.y * 128, n0 = blockIdx.x * 128;

    float acc[4][4][4];
#pragma unroll
    for (int i = 0; i < 4; ++i)
#pragma unroll
        for (int j = 0; j < 4; ++j)
#pragma unroll
            for (int q = 0; q < 4; ++q) acc[i][j][q] = 0.f;

    float4 px[4], pw[4];
#pragma unroll
    for (int i = 0; i < 4; ++i) {
        int e = t + i * 256, r = e >> 3, q = e & 7;
        px[i] = *reinterpret_cast<const float4*>(X  + (size_t)(m0 + r) * 256 + q * 4);
        pw[i] = *reinterpret_cast<const float4*>(Wt + (size_t)(n0 + r) * 256 + q * 4);
    }

    for (int c = 0; c < 8; ++c) {
        __syncthreads();   // compute of c-1 done
#pragma unroll
        for (int i = 0; i < 4; ++i) {
            int e = t + i * 256, r = e >> 3, q = e & 7;
            int base = r * 36 + q * 4;
            float vx[4] = {px[i].x, px[i].y, px[i].z, px[i].w};
            float vw[4] = {pw[i].x, pw[i].y, pw[i].z, pw[i].w};
#pragma unroll
            for (int j = 0; j < 4; ++j) {
                float xh = __uint_as_float(f2tf32(vx[j]));
                xs_h[base + j] = xh;
                xs_l[base + j] = __uint_as_float(f2tf32(vx[j] - xh));
                float wh = __uint_as_float(f2tf32(vw[j]));
                ws_h[base + j] = wh;
                ws_l[base + j] = __uint_as_float(f2tf32(vw[j] - wh));
            }
        }
        if (c < 7) {
#pragma unroll
            for (int i = 0; i < 4; ++i) {
                int e = t + i * 256, r = e >> 3, q = e & 7;
                px[i] = *reinterpret_cast<const float4*>(
                    X  + (size_t)(m0 + r) * 256 + (c + 1) * 32 + q * 4);
                pw[i] = *reinterpret_cast<const float4*>(
                    Wt + (size_t)(n0 + r) * 256 + (c + 1) * 32 + q * 4);
            }
        }
        __syncthreads();   // stage ready

#pragma unroll
        for (int ks = 0; ks < 4; ++ks) {
            const int cc = ks * 8 + (lane & 3);
            uint32_t bh[4][2], bl[4][2];
#pragma unroll
            for (int nt = 0; nt < 4; ++nt) {
                int n = wn * 32 + nt * 8 + (lane >> 2);
                bh[nt][0] = __float_as_uint(ws_h[n * 36 + cc]);
                bh[nt][1] = __float_as_uint(ws_h[n * 36 + cc + 4]);
                bl[nt][0] = __float_as_uint(ws_l[n * 36 + cc]);
                bl[nt][1] = __float_as_uint(ws_l[n * 36 + cc + 4]);
            }
#pragma unroll
            for (int mt = 0; mt < 4; ++mt) {
                int r0 = wm * 64 + mt * 16 + (lane >> 2);
                uint32_t ah[4], al[4];
                ah[0] = __float_as_uint(xs_h[r0 * 36 + cc]);
                ah[1] = __float_as_uint(xs_h[(r0 + 8) * 36 + cc]);
                ah[2] = __float_as_uint(xs_h[r0 * 36 + cc + 4]);
                ah[3] = __float_as_uint(xs_h[(r0 + 8) * 36 + cc + 4]);
                al[0] = __float_as_uint(xs_l[r0 * 36 + cc]);
                al[1] = __float_as_uint(xs_l[(r0 + 8) * 36 + cc]);
                al[2] = __float_as_uint(xs_l[r0 * 36 + cc + 4]);
                al[3] = __float_as_uint(xs_l[(r0 + 8) * 36 + cc + 4]);
#pragma unroll
                for (int nt = 0; nt < 4; ++nt) {
                    mma_tf32(acc[mt][nt], ah, bh[nt][0], bh[nt][1]);
                    mma_tf32(acc[mt][nt], ah, bl[nt][0], bl[nt][1]);
                    mma_tf32(acc[mt][nt], al, bh[nt][0], bh[nt][1]);
                }
            }
        }
    }

    // epilogue: + bias
#pragma unroll
    for (int mt = 0; mt < 4; ++mt)
#pragma unroll
        for (int nt = 0; nt < 4; ++nt) {
            int n = n0 + wn * 32 + nt * 8 + (lane & 3) * 2;
            float b0 = bias[n], b1 = bias[n + 1];
#pragma unroll
            for (int hf = 0; hf < 2; ++hf) {
                int m = m0 + wm * 64 + mt * 16 + (lane >> 2) + hf * 8;
                float2 vv = make_float2(acc[mt][nt][hf * 2] + b0,
                                        acc[mt][nt][hf * 2 + 1] + b1);
                *reinterpret_cast<float2*>(C + (size_t)m * 256 + n) = vv;
            }
        }
}

// ---------------- attention -> normalized adjacency (proven) ----------------
__global__ __launch_bounds__(256) void attn_k(
    const float* __restrict__ Q, const float* __restrict__ Kmat,
    float* __restrict__ Aout)
{
    extern __shared__ float sm[];
    float* qs  = sm;
    float* ks  = sm + 4096;
    float* adj = sm + 8192;
    __shared__ float deg[64];

    const int b = blockIdx.x, t = threadIdx.x;
    const int i = t >> 2, g = t & 3;

    for (int e = t; e < 4096; e += 256) adj[e] = 0.f;

    for (int h = 0; h < 4; ++h) {
        __syncthreads();
        for (int e = t; e < 4096; e += 256) {
            int n = e >> 6, d = e & 63;
            size_t base = ((size_t)b * 64 + n) * 256 + h * 64 + d;
            qs[e] = Q[base];
            ks[e] = Kmat[base];
        }
        __syncthreads();

        float s[16];
#pragma unroll
        for (int jj = 0; jj < 16; ++jj) s[jj] = 0.f;
        for (int d = 0; d < 64; ++d) {
            float qv = qs[i * 64 + d];
#pragma unroll
            for (int jj = 0; jj < 16; ++jj)
                s[jj] += qv * ks[(g * 16 + jj) * 64 + d];
        }
        float mx = -INFINITY;
#pragma unroll
        for (int jj = 0; jj < 16; ++jj) { s[jj] *= 1.25e8f; mx = fmaxf(mx, s[jj]); }
        mx = fmaxf(mx, __shfl_xor_sync(0xffffffffu, mx, 1));
        mx = fmaxf(mx, __shfl_xor_sync(0xffffffffu, mx, 2));
        float sum = 0.f;
#pragma unroll
        for (int jj = 0; jj < 16; ++jj) { s[jj] = __expf(s[jj] - mx); sum += s[jj]; }
        sum += __shfl_xor_sync(0xffffffffu, sum, 1);
        sum += __shfl_xor_sync(0xffffffffu, sum, 2);
        float inv = 0.25f / sum;
#pragma unroll
        for (int jj = 0; jj < 16; ++jj)
            adj[i * 64 + g * 16 + jj] += s[jj] * inv;
    }
    __syncthreads();

    float sv[16];
#pragma unroll
    for (int jj = 0; jj < 16; ++jj) {
        int j = g * 16 + jj;
        sv[jj] = 0.5f * (adj[i * 64 + j] + adj[j * 64 + i]);
    }
    __syncthreads();
#pragma unroll
    for (int jj = 0; jj < 16; ++jj) adj[i * 64 + g * 16 + jj] = sv[jj];

    float ds = 0.f;
#pragma unroll
    for (int jj = 0; jj < 16; ++jj) ds += sv[jj];
    ds += __shfl_xor_sync(0xffffffffu, ds, 1);
    ds += __shfl_xor_sync(0xffffffffu, ds, 2);
    if (g == 0) deg[i] = rsqrtf(ds);
    __syncthreads();

    float di = deg[i];
#pragma unroll
    for (int jj = 0; jj < 16; ++jj) {
        int j = g * 16 + jj;
        Aout[(size_t)b * 4096 + i * 64 + j] = di * adj[i * 64 + j] * deg[j];
    }
}

// ---------------- Chebyshev z-build on tensor cores (bf16x3 mma, proven) ----------------
#define LTH 0
#define LTL 4608
#define CHH 9216
#define CHL 17920
#define Z1H 26624
#define Z1L 35328
#define CHEB_SMEM (44032 * 2)

__device__ __forceinline__ void cheb_step(
    uint32_t sb, int wm, int wn, int lane, int srcH, int srcL, float acc[2][4][4])
{
#pragma unroll
    for (int i = 0; i < 2; ++i)
#pragma unroll
        for (int j = 0; j < 4; ++j)
#pragma unroll
            for (int q = 0; q < 4; ++q) acc[i][j][q] = 0.f;

#pragma unroll
    for (int ks = 0; ks < 4; ++ks) {
        uint32_t ahr[2][4], alr[2][4];
#pragma unroll
        for (int mt = 0; mt < 2; ++mt) {
            uint32_t ao = sb + 2 * ((wm * 32 + mt * 16 + (lane & 15)) * 72
                                    + ks * 16 + (lane >> 4) * 8);
            ldsm_x4(ahr[mt], ao + 2 * LTH);
            ldsm_x4(alr[mt], ao + 2 * LTL);
        }
        uint32_t bh[2][4], bl[2][4];
#pragma unroll
        for (int np = 0; np < 2; ++np) {
            uint32_t bo = sb + 2 * ((ks * 16 + (lane & 15)) * 136
                                    + wn * 32 + np * 16 + (lane >> 4) * 8);
            ldsm_x4t(bh[np], bo + 2 * srcH);
            ldsm_x4t(bl[np], bo + 2 * srcL);
        }
#pragma unroll
        for (int mt = 0; mt < 2; ++mt)
#pragma unroll
            for (int np = 0; np < 2; ++np)
#pragma unroll
                for (int s = 0; s < 2; ++s) {
                    int nt = np * 2 + s;
                    mma_bf16(acc[mt][nt], ahr[mt], bh[np][2 * s], bh[np][2 * s + 1]);
                    mma_bf16(acc[mt][nt], ahr[mt], bl[np][2 * s], bl[np][2 * s + 1]);
                    mma_bf16(acc[mt][nt], alr[mt], bh[np][2 * s], bh[np][2 * s + 1]);
                }
    }
}

__global__ __launch_bounds__(256, 2) void cheb_mma(
    const float* __restrict__ Aglob,
    __nv_bfloat16* __restrict__ zhi, __nv_bfloat16* __restrict__ zlo)
{
    extern __shared__ __nv_bfloat16 S[];
    const uint32_t sb = smem_u32(S);
    const int b = blockIdx.y, f0 = blockIdx.x * 128;
    const int t = threadIdx.x, lane = t & 31, w = t >> 5;
    const int wm = w >> 2, wn = w & 3;

    {
        const float4* Ab = reinterpret_cast<const float4*>(Aglob + (size_t)b * 4096);
#pragma unroll
        for (int i = 0; i < 4; ++i) {
            int e = i * 256 + t;
            int r = e >> 4, q = (e & 15) * 4;
            float4 v = Ab[e];
            float vv[4] = {-v.x, -v.y, -v.z, -v.w};
            __nv_bfloat16 hh[4], ll[4];
#pragma unroll
            for (int j = 0; j < 4; ++j) bsplit(vv[j], hh[j], ll[j]);
            __nv_bfloat162 p0; p0.x = hh[0]; p0.y = hh[1];
            __nv_bfloat162 p1; p1.x = hh[2]; p1.y = hh[3];
            __nv_bfloat162 q0; q0.x = ll[0]; q0.y = ll[1];
            __nv_bfloat162 q1; q1.x = ll[2]; q1.y = ll[3];
            *reinterpret_cast<__nv_bfloat162*>(&S[LTH + r * 72 + q])     = p0;
            *reinterpret_cast<__nv_bfloat162*>(&S[LTH + r * 72 + q + 2]) = p1;
            *reinterpret_cast<__nv_bfloat162*>(&S[LTL + r * 72 + q])     = q0;
            *reinterpret_cast<__nv_bfloat162*>(&S[LTL + r * 72 + q + 2]) = q1;
        }
    }
    {
#pragma unroll
        for (int i = 0; i < 4; ++i) {
            int e = i * 256 + t;
            int r = e >> 4, q = (e & 15) * 8;
            size_t src = (size_t)(b * 64 + r) * 768 + f0 + q;
            *reinterpret_cast<uint4*>(&S[CHH + r * 136 + q]) =
                *reinterpret_cast<const uint4*>(zhi + src);
            *reinterpret_cast<uint4*>(&S[CHL + r * 136 + q]) =
                *reinterpret_cast<const uint4*>(zlo + src);
        }
    }
    __syncthreads();

    float acc[2][4][4];

    cheb_step(sb, wm, wn, lane, CHH, CHL, acc);
#pragma unroll
    for (int mt = 0; mt < 2; ++mt)
#pragma unroll
        for (int nt = 0; nt < 4; ++nt) {
            int col = wn * 32 + nt * 8 + (lane & 3) * 2;
#pragma unroll
            for (int hf = 0; hf < 2; ++hf) {
                int row = wm * 32 + mt * 16 + (lane >> 2) + hf * 8;
                float v0 = acc[mt][nt][hf * 2], v1 = acc[mt][nt][hf * 2 + 1];
                __nv_bfloat16 h0, l0, h1, l1;
                bsplit(v0, h0, l0); bsplit(v1, h1, l1);
                __nv_bfloat162 ph; ph.x = h0; ph.y = h1;
                __nv_bfloat162 pl; pl.x = l0; pl.y = l1;
                *reinterpret_cast<__nv_bfloat162*>(&S[Z1H + row * 136 + col]) = ph;
                *reinterpret_cast<__nv_bfloat162*>(&S[Z1L + row * 136 + col]) = pl;
                size_t zo = (size_t)(b * 64 + row) * 768 + 256 + f0 + col;
                *reinterpret_cast<__nv_bfloat162*>(zhi + zo) = ph;
                *reinterpret_cast<__nv_bfloat162*>(zlo + zo) = pl;
            }
        }
    __syncthreads();

    cheb_step(sb, wm, wn, lane, Z1H, Z1L, acc);
#pragma unroll
    for (int mt = 0; mt < 2; ++mt)
#pragma unroll
        for (int nt = 0; nt < 4; ++nt) {
            int col = wn * 32 + nt * 8 + (lane & 3) * 2;
#pragma unroll
            for (int hf = 0; hf < 2; ++hf) {
                int row = wm * 32 + mt * 16 + (lane >> 2) + hf * 8;
                __nv_bfloat162 hh = *reinterpret_cast<const __nv_bfloat162*>(&S[CHH + row * 136 + col]);
                __nv_bfloat162 hl = *reinterpret_cast<const __nv_bfloat162*>(&S[CHL + row * 136 + col]);
                float b0 = __bfloat162float(hh.x) + __bfloat162float(hl.x);
                float b1 = __bfloat162float(hh.y) + __bfloat162float(hl.y);
                float v0 = 2.f * acc[mt][nt][hf * 2]     - b0;
                float v1 = 2.f * acc[mt][nt][hf * 2 + 1] - b1;
                __nv_bfloat16 h0, l0, h1, l1;
                bsplit(v0, h0, l0); bsplit(v1, h1, l1);
                __nv_bfloat162 ph; ph.x = h0; ph.y = h1;
                __nv_bfloat162 pl; pl.x = l0; pl.y = l1;
                size_t zo = (size_t)(b * 64 + row) * 768 + 512 + f0 + col;
                *reinterpret_cast<__nv_bfloat162*>(zhi + zo) = ph;
                *reinterpret_cast<__nv_bfloat162*>(zlo + zo) = pl;
            }
        }
}

// ---------------- theta GEMM: bf16x3 mma, M=128 N=128, double-buffered smem ----------------
#define TH_SMEM (40960 * 2)

__global__ __launch_bounds__(512, 1) void theta_mma(
    const __nv_bfloat16* __restrict__ Zhi, const __nv_bfloat16* __restrict__ Zlo,
    const __nv_bfloat16* __restrict__ THh, const __nv_bfloat16* __restrict__ THl,
    float* __restrict__ Vout, __nv_bfloat16* __restrict__ zhi,
    __nv_bfloat16* __restrict__ zlo, int writeZ, int layer)
{
    extern __shared__ __nv_bfloat16 S[];   // 2 x 20480
    const uint32_t sb = smem_u32(S);
    const int t = threadIdx.x, lane = t & 31, w = t >> 5;
    const int wm = w >> 2, wn = w & 3;
    const int m0 = blockIdx.y * 128, n0 = blockIdx.x * 128;

    float acc[2][4][4];
#pragma unroll
    for (int i = 0; i < 2; ++i)
#pragma unroll
        for (int j = 0; j < 4; ++j)
#pragma unroll
            for (int q = 0; q < 4; ++q) acc[i][j][q] = 0.f;

    const int ar = t >> 2, as = (t & 3) * 8;
    const size_t aSrc = (size_t)(m0 + ar) * 768 + as;
    const size_t bSrc = (size_t)(n0 + ar) * 768 + as;
    const int dOff = ar * 40 + as;

    uint4 pa0 = *reinterpret_cast<const uint4*>(Zhi + aSrc);
    uint4 pa1 = *reinterpret_cast<const uint4*>(Zlo + aSrc);
    uint4 pb0 = *reinterpret_cast<const uint4*>(THh + bSrc);
    uint4 pb1 = *reinterpret_cast<const uint4*>(THl + bSrc);
    *reinterpret_cast<uint4*>(&S[dOff])         = pa0;
    *reinterpret_cast<uint4*>(&S[5120 + dOff])  = pa1;
    *reinterpret_cast<uint4*>(&S[10240 + dOff]) = pb0;
    *reinterpret_cast<uint4*>(&S[15360 + dOff]) = pb1;
    __syncthreads();

    const uint32_t aAddr = sb + 2 * ((wm * 32 + (lane & 15)) * 40 + (lane >> 4) * 8);
    const uint32_t bAddr = sb + 2 * (10240 + (wn * 32 + (lane & 15)) * 40 + (lane >> 4) * 8);

    for (int c = 0; c < 24; ++c) {
        const int cur = c & 1;
        const uint32_t bOff = cur * 40960;   // bytes
        if (c < 23) {
            size_t ka = aSrc + (c + 1) * 32, kb = bSrc + (c + 1) * 32;
            pa0 = *reinterpret_cast<const uint4*>(Zhi + ka);
            pa1 = *reinterpret_cast<const uint4*>(Zlo + ka);
            pb0 = *reinterpret_cast<const uint4*>(THh + kb);
            pb1 = *reinterpret_cast<const uint4*>(THl + kb);
        }

#pragma unroll
        for (int ks = 0; ks < 2; ++ks) {
            uint32_t ahr[2][4], alr[2][4], bhr[2][4], blr[2][4];
#pragma unroll
            for (int mt = 0; mt < 2; ++mt) {
                uint32_t off = bOff + 2 * (mt * 16 * 40 + ks * 16);
                ldsm_x4(ahr[mt], aAddr + off);
                ldsm_x4(alr[mt], aAddr + 2 * 5120 + off);
            }
#pragma unroll
            for (int np = 0; np < 2; ++np) {
                uint32_t off = bOff + 2 * (np * 16 * 40 + ks * 16);
                ldsm_x4(bhr[np], bAddr + off);
                ldsm_x4(blr[np], bAddr + 2 * 5120 + off);
            }
#pragma unroll
            for (int mt = 0; mt < 2; ++mt)
#pragma unroll
                for (int nt = 0; nt < 4; ++nt) {
                    int np = nt >> 1, s = nt & 1;
                    mma_bf16(acc[mt][nt], ahr[mt], bhr[np][s], bhr[np][s + 2]);
                    mma_bf16(acc[mt][nt], ahr[mt], blr[np][s], blr[np][s + 2]);
                    mma_bf16(acc[mt][nt], alr[mt], bhr[np][s], bhr[np][s + 2]);
                }
        }

        if (c < 23) {
            int o = (cur ^ 1) * 20480 + dOff;
            *reinterpret_cast<uint4*>(&S[o])         = pa0;
            *reinterpret_cast<uint4*>(&S[o + 5120])  = pa1;
            *reinterpret_cast<uint4*>(&S[o + 10240]) = pb0;
            *reinterpret_cast<uint4*>(&S[o + 15360]) = pb1;
            __syncthreads();
        }
    }

#pragma unroll
    for (int mt = 0; mt < 2; ++mt)
#pragma unroll
        for (int nt = 0; nt < 4; ++nt) {
            int np = nt >> 1, s = nt & 1;
            int n = n0 + wn * 32 + np * 16 + s * 8 + (lane & 3) * 2;
#pragma unroll
            for (int hf = 0; hf < 2; ++hf) {
                int m = m0 + wm * 32 + mt * 16 + (lane >> 2) + hf * 8;
                float v0 = fmaxf(acc[mt][nt][hf * 2],     0.f);
                float v1 = fmaxf(acc[mt][nt][hf * 2 + 1], 0.f);
                int b = m >> 6, nd = m & 63;
                float2 vv = make_float2(v0, v1);
                *reinterpret_cast<float2*>(
                    Vout + ((size_t)(b * NLAYER + layer) * 64 + nd) * 256 + n) = vv;
                if (writeZ) {
                    __nv_bfloat16 h0, l0, h1, l1;
                    bsplit(v0, h0, l0); bsplit(v1, h1, l1);
                    __nv_bfloat162 ph; ph.x = h0; ph.y = h1;
                    __nv_bfloat162 pl; pl.x = l0; pl.y = l1;
                    *reinterpret_cast<__nv_bfloat162*>(zhi + (size_t)m * 768 + n) = ph;
                    *reinterpret_cast<__nv_bfloat162*>(zlo + (size_t)m * 768 + n) = pl;
                }
            }
        }
}

// ---------------- launcher ----------------
extern "C" void kernel_launch(void* const* d_in, const int* in_sizes, int n_in,
                              void* d_out, int out_size)
{
    const float* x     = (const float*)d_in[0];
    const float* Wq    = (const float*)d_in[1];
    const float* bq    = (const float*)d_in[2];
    const float* Wk    = (const float*)d_in[3];
    const float* bk    = (const float*)d_in[4];
    const float* theta = (const float*)d_in[5];

    float* out  = (float*)d_out;
    float* Vout = out;
    float* Aout = out + VELEMS;

    __nv_bfloat16 *Zhi, *Zlo, *THhi, *THlo;
    float *Qb, *Kb, *Wt;
    cudaGetSymbolAddress((void**)&Zhi, g_Zhi);
    cudaGetSymbolAddress((void**)&Zlo, g_Zlo);
    cudaGetSymbolAddress((void**)&THhi, g_THhi);
    cudaGetSymbolAddress((void**)&THlo, g_THlo);
    cudaGetSymbolAddress((void**)&Qb, g_Q);
    cudaGetSymbolAddress((void**)&Kb, g_K);
    cudaGetSymbolAddress((void**)&Wt, g_Wt);

    cudaFuncSetAttribute(attn_k, cudaFuncAttributeMaxDynamicSharedMemorySize, 49152);
    cudaFuncSetAttribute(cheb_mma, cudaFuncAttributeMaxDynamicSharedMemorySize, CHEB_SMEM);
    cudaFuncSetAttribute(qk_tf32, cudaFuncAttributeMaxDynamicSharedMemorySize, QK_SMEM);
    cudaFuncSetAttribute(theta_mma, cudaFuncAttributeMaxDynamicSharedMemorySize, TH_SMEM);

    split_x_k<<<16384, 256>>>(x, Zhi, Zlo);
    prep_wt_k<<<512, 256>>>(Wq, Wk, Wt);
    prep_th_k<<<3072, 256>>>(theta, THhi, THlo);

    dim3 qkGrid(2, 512);
    qk_tf32<<<qkGrid, 256, QK_SMEM>>>(x, Wt, bq, Qb);
    qk_tf32<<<qkGrid, 256, QK_SMEM>>>(x, Wt + 65536, bk, Kb);

    attn_k<<<B_SZ, 256, 49152>>>(Qb, Kb, Aout);

    dim3 chGrid(2, B_SZ);
    dim3 thGrid(2, 512);
    for (int l = 0; l < NLAYER; ++l) {
        cheb_mma<<<chGrid, 256, CHEB_SMEM>>>(Aout, Zhi, Zlo);
        theta_mma<<<thGrid, 512, TH_SMEM>>>(Zhi, Zlo,
                                   THhi + (size_t)l * 196608, THlo + (size_t)l * 196608,
                                   Vout, Zhi, Zlo, (l < 3) ? 1 : 0, l);
    }
}